// round 4
// baseline (speedup 1.0000x reference)
#include <cuda_runtime.h>
#include <cuda_bf16.h>
#include <math.h>
#include <stdint.h>

// Problem constants
#define BATCH 8192
#define SDIM  70
#define NS    64
#define HID   1024
#define NACT  4096
#define LOG_EPS (-20.723265836946407f)   // logf(1e-9f)

// ---------------------------------------------------------------------------
// Scratch (allocation-free __device__ globals)
// ---------------------------------------------------------------------------
__device__ __align__(16) __nv_bfloat16 g_h1h[BATCH * HID];
__device__ __align__(16) __nv_bfloat16 g_h1l[BATCH * HID];
__device__ __align__(16) __nv_bfloat16 g_h2h[BATCH * HID];
__device__ __align__(16) __nv_bfloat16 g_h2l[BATCH * HID];
__device__ __align__(16) __nv_bfloat16 g_W2Th[HID * HID];
__device__ __align__(16) __nv_bfloat16 g_W2Tl[HID * HID];
__device__ __align__(16) __nv_bfloat16 g_WhTh[NACT * HID];
__device__ __align__(16) __nv_bfloat16 g_WhTl[NACT * HID];

// ---------------------------------------------------------------------------
// Helpers (plain sm_80+ PTX only — nothing sm_103a-conditional)
// ---------------------------------------------------------------------------
__device__ __forceinline__ uint32_t smem_u32(const void* p) {
    uint32_t a;
    asm("{ .reg .u64 t; cvta.to.shared.u64 t, %1; cvt.u32.u64 %0, t; }" : "=r"(a) : "l"(p));
    return a;
}

__device__ __forceinline__ void cp_async16(uint32_t saddr, const void* gaddr) {
    asm volatile("cp.async.cg.shared.global [%0], [%1], 16;" :: "r"(saddr), "l"(gaddr));
}
#define CP_COMMIT()  asm volatile("cp.async.commit_group;" ::: "memory")
#define CP_WAIT(n)   asm volatile("cp.async.wait_group %0;" :: "n"(n) : "memory")

__device__ __forceinline__ void ldsm_x4(uint32_t* r, uint32_t addr) {
    asm volatile("ldmatrix.sync.aligned.m8n8.x4.shared.b16 {%0,%1,%2,%3}, [%4];"
        : "=r"(r[0]), "=r"(r[1]), "=r"(r[2]), "=r"(r[3]) : "r"(addr));
}

__device__ __forceinline__ void mma16816(float* d, const uint32_t* a, const uint32_t* b) {
    asm volatile("mma.sync.aligned.m16n8k16.row.col.f32.bf16.bf16.f32 "
        "{%0,%1,%2,%3}, {%4,%5,%6,%7}, {%8,%9}, {%0,%1,%2,%3};"
        : "+f"(d[0]), "+f"(d[1]), "+f"(d[2]), "+f"(d[3])
        : "r"(a[0]), "r"(a[1]), "r"(a[2]), "r"(a[3]), "r"(b[0]), "r"(b[1]));
}

// ---------------------------------------------------------------------------
// HMMA GEMM:  C[M, Ntot] = act( A[M,K] @ B^T + bias ),  bf16 hi/lo split.
//   A as Ah/Al [M,K];  B as Bh/Bl [Ntot,K] (K-major).
//   Virtual K' = 3K:  seg0 Ah*Bh, seg1 Al*Bh, seg2 Ah*Bl.
// CTA tile 128 x 256, K-tile 64, 8 warps in 2(m) x 4(n); warp tile 64 x 64.
// 3-stage cp.async ring, one __syncthreads per K-tile, fragment double-buffer.
// Smem rows are 128B (64 bf16) with XOR-8 chunk swizzle.
// ---------------------------------------------------------------------------
#define TM 128
#define TN 256
#define KT 64
#define STAGE_BYTES ((TM + TN) * 128)      // 49152
#define NSTAGE 3
#define HMMA_SMEM (NSTAGE * STAGE_BYTES)   // 147456

template <int OUT>
__global__ __launch_bounds__(256, 1)
void hmma_gemm(const __nv_bfloat16* __restrict__ Ah, const __nv_bfloat16* __restrict__ Al,
               const __nv_bfloat16* __restrict__ Bh, const __nv_bfloat16* __restrict__ Bl,
               const float* __restrict__ bias,
               float* __restrict__ Cf,
               __nv_bfloat16* __restrict__ Ch, __nv_bfloat16* __restrict__ Cl,
               int K, int Ntot)
{
    extern __shared__ char smem_raw[];
    const uint32_t sbase = smem_u32(smem_raw);

    const int tid  = threadIdx.x;
    const int lane = tid & 31;
    const int wid  = tid >> 5;
    const int wm   = wid & 1;          // 2 warps along M (64 rows each)
    const int wn   = wid >> 1;         // 4 warps along N (64 cols each)
    const int bm   = blockIdx.y * TM;
    const int bn   = blockIdx.x * TN;
    const int nst  = (3 * K) / KT;     // 48 for K=1024

    float acc[4][8][4];
#pragma unroll
    for (int i = 0; i < 4; i++)
#pragma unroll
        for (int j = 0; j < 8; j++)
#pragma unroll
            for (int q = 0; q < 4; q++) acc[i][j][q] = 0.0f;

    // ---- stage loader: A 1024 chunks (4/thread) + B 2048 chunks (8/thread) --
    auto load_stage = [&](int i, int s) {
        const int kk0 = i * KT;
        const int seg = kk0 / K;
        const int kl  = kk0 - seg * K;
        const __nv_bfloat16* Asrc = (seg == 1) ? Al : Ah;
        const __nv_bfloat16* Bsrc = (seg == 2) ? Bl : Bh;
        const uint32_t sA = sbase + s * STAGE_BYTES;
        const uint32_t sB = sA + TM * 128;
#pragma unroll
        for (int p = 0; p < 4; p++) {
            const int idx = p * 256 + tid;
            const int r = idx >> 3, c = idx & 7;
            cp_async16(sA + r * 128 + ((c ^ (r & 7)) << 4),
                       Asrc + (size_t)(bm + r) * K + kl + c * 8);
        }
#pragma unroll
        for (int p = 0; p < 8; p++) {
            const int idx = p * 256 + tid;
            const int r = idx >> 3, c = idx & 7;
            cp_async16(sB + r * 128 + ((c ^ (r & 7)) << 4),
                       Bsrc + (size_t)(bn + r) * K + kl + c * 8);
        }
    };

    load_stage(0, 0); CP_COMMIT();
    load_stage(1, 1); CP_COMMIT();

    // fragment ring buffers (double-buffered across k16 sub-steps)
    uint32_t afr[2][4][4], bfr[2][4][4];

    auto ld_frags = [&](int buf, uint32_t sA, uint32_t sB, int ks) {
#pragma unroll
        for (int mt = 0; mt < 4; mt++) {
            const int row = wm * 64 + mt * 16 + (lane & 15);
            const int ch  = ks * 2 + (lane >> 4);
            ldsm_x4(afr[buf][mt], sA + row * 128 + ((ch ^ (row & 7)) << 4));
        }
#pragma unroll
        for (int np = 0; np < 4; np++) {
            const int nrow = wn * 64 + np * 16 + ((lane >> 4) << 3) + (lane & 7);
            const int ch   = ks * 2 + ((lane >> 3) & 1);
            ldsm_x4(bfr[buf][np], sB + nrow * 128 + ((ch ^ (nrow & 7)) << 4));
        }
    };

    for (int i = 0; i < nst; i++) {
        const int s = i % NSTAGE;
        CP_WAIT(1);
        __syncthreads();

        // refill the slot freed at the last iteration
        if (i + 2 < nst) load_stage(i + 2, (i + 2) % NSTAGE);
        CP_COMMIT();

        const uint32_t sA = sbase + s * STAGE_BYTES;
        const uint32_t sB = sA + TM * 128;

        ld_frags(0, sA, sB, 0);
#pragma unroll
        for (int ks = 0; ks < KT / 16; ks++) {
            const int cur = ks & 1;
            if (ks + 1 < KT / 16) ld_frags(cur ^ 1, sA, sB, ks + 1);
#pragma unroll
            for (int mt = 0; mt < 4; mt++)
#pragma unroll
                for (int np = 0; np < 4; np++) {
                    mma16816(acc[mt][np * 2 + 0], afr[cur][mt], &bfr[cur][np][0]);
                    mma16816(acc[mt][np * 2 + 1], afr[cur][mt], &bfr[cur][np][2]);
                }
        }
    }

    // ---- epilogue ----
    const int q  = lane & 3;
    const int r4 = lane >> 2;
#pragma unroll
    for (int mt = 0; mt < 4; mt++) {
#pragma unroll
        for (int nt = 0; nt < 8; nt++) {
            const int row0 = bm + wm * 64 + mt * 16 + r4;
            const int col  = bn + wn * 64 + nt * 8 + q * 2;
            const float b0 = bias[col], b1 = bias[col + 1];
            float d0 = acc[mt][nt][0] + b0;
            float d1 = acc[mt][nt][1] + b1;
            float d2 = acc[mt][nt][2] + b0;
            float d3 = acc[mt][nt][3] + b1;
            if (OUT == 0) {
                *reinterpret_cast<float2*>(Cf + (size_t)row0 * Ntot + col) =
                    make_float2(d0, d1);
                *reinterpret_cast<float2*>(Cf + (size_t)(row0 + 8) * Ntot + col) =
                    make_float2(d2, d3);
            } else {
                float t0 = tanhf(d0), t1 = tanhf(d1), t2 = tanhf(d2), t3 = tanhf(d3);
                __nv_bfloat16 h0 = __float2bfloat16(t0), h1 = __float2bfloat16(t1);
                __nv_bfloat16 h2 = __float2bfloat16(t2), h3 = __float2bfloat16(t3);
                __nv_bfloat162 hv01 = __nv_bfloat162(h0, h1);
                __nv_bfloat162 hv23 = __nv_bfloat162(h2, h3);
                __nv_bfloat162 lv01 = __nv_bfloat162(
                    __float2bfloat16(t0 - __bfloat162float(h0)),
                    __float2bfloat16(t1 - __bfloat162float(h1)));
                __nv_bfloat162 lv23 = __nv_bfloat162(
                    __float2bfloat16(t2 - __bfloat162float(h2)),
                    __float2bfloat16(t3 - __bfloat162float(h3)));
                *reinterpret_cast<__nv_bfloat162*>(Ch + (size_t)row0 * Ntot + col) = hv01;
                *reinterpret_cast<__nv_bfloat162*>(Ch + (size_t)(row0 + 8) * Ntot + col) = hv23;
                *reinterpret_cast<__nv_bfloat162*>(Cl + (size_t)row0 * Ntot + col) = lv01;
                *reinterpret_cast<__nv_bfloat162*>(Cl + (size_t)(row0 + 8) * Ntot + col) = lv23;
            }
        }
    }
}

// ---------------------------------------------------------------------------
// GEMM1 (fp32, K=70): h1 = tanh(states @ W1 + b1), split-stored as bf16 hi/lo
// ---------------------------------------------------------------------------
__global__ __launch_bounds__(256, 2)
void sgemm_split(const float* __restrict__ A, const float* __restrict__ B,
                 const float* __restrict__ bias,
                 __nv_bfloat16* __restrict__ Chh, __nv_bfloat16* __restrict__ Cll,
                 int M, int N, int K)
{
    __shared__ float As[8][128];
    __shared__ float Bs[8][128];

    const int tid = threadIdx.x;
    const int bm = blockIdx.y * 128, bn = blockIdx.x * 128;
    const int tm = (tid >> 4) * 8, tn = (tid & 15) * 8;

    float acc[8][8];
#pragma unroll
    for (int i = 0; i < 8; i++)
#pragma unroll
        for (int j = 0; j < 8; j++) acc[i][j] = 0.0f;

    const int aM = (tid * 4) >> 3, aK = (tid * 4) & 7;
    const int bK = (tid * 4) >> 7, bN = (tid * 4) & 127;

    for (int k0 = 0; k0 < K; k0 += 8) {
#pragma unroll
        for (int i = 0; i < 4; i++) {
            int kk = aK + i;
            float v = 0.0f;
            if (k0 + kk < K) v = A[(size_t)(bm + aM) * K + k0 + kk];
            As[kk][aM] = v;
        }
        if (k0 + bK < K)
            *reinterpret_cast<float4*>(&Bs[bK][bN]) =
                *reinterpret_cast<const float4*>(&B[(size_t)(k0 + bK) * N + bn + bN]);
        else
            *reinterpret_cast<float4*>(&Bs[bK][bN]) = make_float4(0.f, 0.f, 0.f, 0.f);
        __syncthreads();

#pragma unroll
        for (int k = 0; k < 8; k++) {
            float a[8], b[8];
#pragma unroll
            for (int h = 0; h < 2; h++) {
                float4 t = *reinterpret_cast<const float4*>(&As[k][tm + h * 4]);
                a[h*4] = t.x; a[h*4+1] = t.y; a[h*4+2] = t.z; a[h*4+3] = t.w;
            }
#pragma unroll
            for (int h = 0; h < 2; h++) {
                float4 t = *reinterpret_cast<const float4*>(&Bs[k][tn + h * 4]);
                b[h*4] = t.x; b[h*4+1] = t.y; b[h*4+2] = t.z; b[h*4+3] = t.w;
            }
#pragma unroll
            for (int i = 0; i < 8; i++)
#pragma unroll
                for (int j = 0; j < 8; j++)
                    acc[i][j] = fmaf(a[i], b[j], acc[i][j]);
        }
        __syncthreads();
    }

#pragma unroll
    for (int i = 0; i < 8; i++) {
        union { uint4 u; __nv_bfloat16 b[8]; } H, L;
#pragma unroll
        for (int j = 0; j < 8; j++) {
            float v = tanhf(acc[i][j] + bias[bn + tn + j]);
            __nv_bfloat16 hi = __float2bfloat16(v);
            H.b[j] = hi;
            L.b[j] = __float2bfloat16(v - __bfloat162float(hi));
        }
        *reinterpret_cast<uint4*>(&Chh[(size_t)(bm + tm + i) * N + bn + tn]) = H.u;
        *reinterpret_cast<uint4*>(&Cll[(size_t)(bm + tm + i) * N + bn + tn]) = L.u;
    }
}

// ---------------------------------------------------------------------------
// Weight prep: W[K,N] fp32 -> Wt_hi/Wt_lo [N,K] bf16 (transpose + split)
// ---------------------------------------------------------------------------
__global__ void transpose_split(const float* __restrict__ W,
                                __nv_bfloat16* __restrict__ Th,
                                __nv_bfloat16* __restrict__ Tl, int K, int N)
{
    __shared__ float t[32][33];
    const int k0 = blockIdx.x * 32, n0 = blockIdx.y * 32;
    const int tx = threadIdx.x, ty = threadIdx.y;
    for (int j = ty; j < 32; j += 8)
        t[j][tx] = W[(size_t)(k0 + j) * N + n0 + tx];
    __syncthreads();
    for (int j = ty; j < 32; j += 8) {
        float v = t[tx][j];
        __nv_bfloat16 hi = __float2bfloat16(v);
        Th[(size_t)(n0 + j) * K + k0 + tx] = hi;
        Tl[(size_t)(n0 + j) * K + k0 + tx] = __float2bfloat16(v - __bfloat162float(hi));
    }
}

// ---------------------------------------------------------------------------
// In-place masked softmax
// ---------------------------------------------------------------------------
__global__ __launch_bounds__(256)
void masked_softmax(float* __restrict__ out, const float* __restrict__ states)
{
    const int row = blockIdx.x;
    const int tid = threadIdx.x;

    __shared__ float sred[32];
    __shared__ int scap[6];

    if (tid < 6) scap[tid] = (int)floorf(states[(size_t)row * SDIM + NS + tid]);
    __syncthreads();

    const int c0 = scap[0], c1 = scap[1], c2 = scap[2];
    const int c3 = scap[3], c4 = scap[4], c5 = scap[5];

    float* rowp = out + (size_t)row * NACT;
    float vals[16];
    float mx = -INFINITY;

#pragma unroll
    for (int i = 0; i < 16; i++) {
        int a = tid + i * 256;
        float v = rowp[a];
        bool feas = (((a >> 10) & 3) <= c0) && (((a >> 8) & 3) <= c1) &&
                    (((a >> 6) & 3) <= c2) && (((a >> 4) & 3) <= c3) &&
                    (((a >> 2) & 3) <= c4) && (((a) & 3) <= c5);
        if (!feas) v += LOG_EPS;
        vals[i] = v;
        mx = fmaxf(mx, v);
    }

#pragma unroll
    for (int o = 16; o > 0; o >>= 1) mx = fmaxf(mx, __shfl_xor_sync(0xffffffffu, mx, o));
    if ((tid & 31) == 0) sred[tid >> 5] = mx;
    __syncthreads();
    if (tid < 32) {
        float m = (tid < 8) ? sred[tid] : -INFINITY;
#pragma unroll
        for (int o = 4; o > 0; o >>= 1) m = fmaxf(m, __shfl_xor_sync(0xffffffffu, m, o));
        if (tid == 0) sred[0] = m;
    }
    __syncthreads();
    mx = sred[0];
    __syncthreads();

    float sum = 0.0f;
#pragma unroll
    for (int i = 0; i < 16; i++) { vals[i] = expf(vals[i] - mx); sum += vals[i]; }

#pragma unroll
    for (int o = 16; o > 0; o >>= 1) sum += __shfl_xor_sync(0xffffffffu, sum, o);
    if ((tid & 31) == 0) sred[tid >> 5] = sum;
    __syncthreads();
    if (tid < 32) {
        float s = (tid < 8) ? sred[tid] : 0.0f;
#pragma unroll
        for (int o = 4; o > 0; o >>= 1) s += __shfl_xor_sync(0xffffffffu, s, o);
        if (tid == 0) sred[0] = s;
    }
    __syncthreads();
    const float inv = 1.0f / sred[0];

#pragma unroll
    for (int i = 0; i < 16; i++)
        rowp[tid + i * 256] = vals[i] * inv;
}

// ---------------------------------------------------------------------------
extern "C" void kernel_launch(void* const* d_in, const int* in_sizes, int n_in,
                              void* d_out, int out_size)
{
    const float* states = (const float*)d_in[0];
    const float* W1     = (const float*)d_in[1];
    const float* b1     = (const float*)d_in[2];
    const float* W2     = (const float*)d_in[3];
    const float* b2     = (const float*)d_in[4];
    const float* Wh     = (const float*)d_in[5];
    const float* bh     = (const float*)d_in[6];
    float* out = (float*)d_out;

    __nv_bfloat16 *h1h, *h1l, *h2h, *h2l, *W2Th, *W2Tl, *WhTh, *WhTl;
    cudaGetSymbolAddress((void**)&h1h,  g_h1h);
    cudaGetSymbolAddress((void**)&h1l,  g_h1l);
    cudaGetSymbolAddress((void**)&h2h,  g_h2h);
    cudaGetSymbolAddress((void**)&h2l,  g_h2l);
    cudaGetSymbolAddress((void**)&W2Th, g_W2Th);
    cudaGetSymbolAddress((void**)&W2Tl, g_W2Tl);
    cudaGetSymbolAddress((void**)&WhTh, g_WhTh);
    cudaGetSymbolAddress((void**)&WhTl, g_WhTl);

    cudaFuncSetAttribute(hmma_gemm<0>, cudaFuncAttributeMaxDynamicSharedMemorySize, HMMA_SMEM);
    cudaFuncSetAttribute(hmma_gemm<1>, cudaFuncAttributeMaxDynamicSharedMemorySize, HMMA_SMEM);

    // weight prep (transpose + bf16 split)
    transpose_split<<<dim3(HID / 32, HID / 32), dim3(32, 8)>>>(W2, W2Th, W2Tl, HID, HID);
    transpose_split<<<dim3(HID / 32, NACT / 32), dim3(32, 8)>>>(Wh, WhTh, WhTl, HID, NACT);

    // layer 1 (fp32 SGEMM, K=70) -> h1 split
    sgemm_split<<<dim3(HID / 128, BATCH / 128), 256>>>(states, W1, b1, h1h, h1l,
                                                       BATCH, HID, SDIM);
    // layer 2 (HMMA) -> h2 split
    hmma_gemm<1><<<dim3(HID / TN, BATCH / TM), 256, HMMA_SMEM>>>(
        h1h, h1l, W2Th, W2Tl, b2, nullptr, h2h, h2l, HID, HID);
    // head (HMMA) -> logits fp32 straight into d_out
    hmma_gemm<0><<<dim3(NACT / TN, BATCH / TM), 256, HMMA_SMEM>>>(
        h2h, h2l, WhTh, WhTl, bh, out, nullptr, nullptr, HID, NACT);
    // masked softmax in place
    masked_softmax<<<BATCH, 256>>>(out, states);
}

// round 5
// speedup vs baseline: 1.6218x; 1.6218x over previous
#include <cuda_runtime.h>
#include <cuda_fp16.h>
#include <cuda_bf16.h>
#include <math.h>
#include <stdint.h>

// Problem constants
#define BATCH 8192
#define SDIM  70
#define NS    64
#define HID   1024
#define NACT  4096
#define LOG_EPS (-20.723265836946407f)   // logf(1e-9f)

// ---------------------------------------------------------------------------
// Scratch (allocation-free __device__ globals)
// ---------------------------------------------------------------------------
__device__ __align__(16) __half g_h1h[BATCH * HID];
__device__ __align__(16) __half g_h1l[BATCH * HID];
__device__ __align__(16) __half g_h2h[BATCH * HID];
__device__ __align__(16) __half g_h2l[BATCH * HID];
__device__ __align__(16) __half g_W2T[HID * HID];
__device__ __align__(16) __half g_WhT[NACT * HID];

// ---------------------------------------------------------------------------
// Helpers (plain sm_80+ PTX only — nothing sm_103a-conditional)
// ---------------------------------------------------------------------------
__device__ __forceinline__ uint32_t smem_u32(const void* p) {
    uint32_t a;
    asm("{ .reg .u64 t; cvta.to.shared.u64 t, %1; cvt.u32.u64 %0, t; }" : "=r"(a) : "l"(p));
    return a;
}

__device__ __forceinline__ void cp_async16(uint32_t saddr, const void* gaddr) {
    asm volatile("cp.async.cg.shared.global [%0], [%1], 16;" :: "r"(saddr), "l"(gaddr));
}
#define CP_COMMIT()  asm volatile("cp.async.commit_group;" ::: "memory")
#define CP_WAIT(n)   asm volatile("cp.async.wait_group %0;" :: "n"(n) : "memory")

__device__ __forceinline__ void ldsm_x4(uint32_t* r, uint32_t addr) {
    asm volatile("ldmatrix.sync.aligned.m8n8.x4.shared.b16 {%0,%1,%2,%3}, [%4];"
        : "=r"(r[0]), "=r"(r[1]), "=r"(r[2]), "=r"(r[3]) : "r"(addr));
}

__device__ __forceinline__ void mma16816(float* d, const uint32_t* a, const uint32_t* b) {
    asm volatile("mma.sync.aligned.m16n8k16.row.col.f32.f16.f16.f32 "
        "{%0,%1,%2,%3}, {%4,%5,%6,%7}, {%8,%9}, {%0,%1,%2,%3};"
        : "+f"(d[0]), "+f"(d[1]), "+f"(d[2]), "+f"(d[3])
        : "r"(a[0]), "r"(a[1]), "r"(a[2]), "r"(a[3]), "r"(b[0]), "r"(b[1]));
}

// ---------------------------------------------------------------------------
// HMMA GEMM (fp16 2-term split):
//   C[M,Ntot] = act( (Ah + Al)[M,K] @ B^T + bias ),  Ah/Al fp16 hi/lo, B fp16.
//   B fragments loaded once per K-step and reused for the hi and lo MMAs;
//   both accumulate into the same fp32 accumulator.
// CTA tile 128x128, K-tile 64, 8 warps in 4(m) x 2(n); warp tile 32 x 64.
// 2-stage cp.async, XOR-8 swizzled 128B smem rows (R3-verified layout).
// ---------------------------------------------------------------------------
#define KT 64
#define A_BYTES  16384                 // 128 rows x 128 B
#define STAGE_BYTES (3 * A_BYTES)      // Ah + Al + B = 49152
#define HMMA_SMEM (2 * STAGE_BYTES)    // 98304

template <int OUT>
__global__ __launch_bounds__(256, 2)
void hmma_gemm(const __half* __restrict__ Ah, const __half* __restrict__ Al,
               const __half* __restrict__ B,
               const float* __restrict__ bias,
               float* __restrict__ Cf,
               __half* __restrict__ Ch, __half* __restrict__ Cl,
               int K, int Ntot)
{
    extern __shared__ char smem_raw[];
    const uint32_t sbase = smem_u32(smem_raw);

    const int tid  = threadIdx.x;
    const int lane = tid & 31;
    const int wid  = tid >> 5;
    const int wm   = wid & 3;          // 4 warps along M (32 rows each)
    const int wn   = wid >> 2;         // 2 warps along N (64 cols each)
    const int bm   = blockIdx.y * 128;
    const int bn   = blockIdx.x * 128;
    const int nst  = K / KT;           // 16 for K=1024

    float acc[2][8][4];
#pragma unroll
    for (int i = 0; i < 2; i++)
#pragma unroll
        for (int j = 0; j < 8; j++)
#pragma unroll
            for (int q = 0; q < 4; q++) acc[i][j][q] = 0.0f;

    // ---- stage loader: 3 x 1024 16B chunks (Ah, Al, B), 12 per thread ------
    auto load_stage = [&](int i, int s) {
        const int kl = i * KT;
        const uint32_t sAh = sbase + s * STAGE_BYTES;
        const uint32_t sAl = sAh + A_BYTES;
        const uint32_t sB  = sAl + A_BYTES;
#pragma unroll
        for (int p = 0; p < 4; p++) {
            const int idx = p * 256 + tid;
            const int r = idx >> 3, c = idx & 7;
            const uint32_t so = r * 128 + ((c ^ (r & 7)) << 4);
            cp_async16(sAh + so, Ah + (size_t)(bm + r) * K + kl + c * 8);
            cp_async16(sAl + so, Al + (size_t)(bm + r) * K + kl + c * 8);
            cp_async16(sB  + so, B  + (size_t)(bn + r) * K + kl + c * 8);
        }
        CP_COMMIT();
    };

    load_stage(0, 0);
    load_stage(1, 1);

    for (int i = 0; i < nst; i++) {
        const int s = i & 1;
        if (i + 1 < nst) { CP_WAIT(1); } else { CP_WAIT(0); }
        __syncthreads();

        const uint32_t sAh = sbase + s * STAGE_BYTES;
        const uint32_t sAl = sAh + A_BYTES;
        const uint32_t sB  = sAl + A_BYTES;

#pragma unroll
        for (int ks = 0; ks < KT / 16; ks++) {
            // A fragments (hi and lo): 2 m16 tiles each
            uint32_t ah[2][4], al[2][4];
#pragma unroll
            for (int mt = 0; mt < 2; mt++) {
                const int row = wm * 32 + mt * 16 + (lane & 15);
                const int ch  = ks * 2 + (lane >> 4);
                const uint32_t so = row * 128 + ((ch ^ (row & 7)) << 4);
                ldsm_x4(ah[mt], sAh + so);
                ldsm_x4(al[mt], sAl + so);
            }
            // B fragments: 4 x ldmatrix.x4 (shared by hi and lo MMAs)
            uint32_t b[4][4];
#pragma unroll
            for (int np = 0; np < 4; np++) {
                const int nrow = wn * 64 + np * 16 + ((lane >> 4) << 3) + (lane & 7);
                const int ch   = ks * 2 + ((lane >> 3) & 1);
                ldsm_x4(b[np], sB + nrow * 128 + ((ch ^ (nrow & 7)) << 4));
            }
#pragma unroll
            for (int mt = 0; mt < 2; mt++)
#pragma unroll
                for (int np = 0; np < 4; np++) {
                    mma16816(acc[mt][np * 2 + 0], ah[mt], &b[np][0]);
                    mma16816(acc[mt][np * 2 + 1], ah[mt], &b[np][2]);
                    mma16816(acc[mt][np * 2 + 0], al[mt], &b[np][0]);
                    mma16816(acc[mt][np * 2 + 1], al[mt], &b[np][2]);
                }
        }
        __syncthreads();
        if (i + 2 < nst) load_stage(i + 2, s);
    }

    // ---- epilogue ----
    const int q  = lane & 3;
    const int r4 = lane >> 2;
#pragma unroll
    for (int mt = 0; mt < 2; mt++) {
#pragma unroll
        for (int nt = 0; nt < 8; nt++) {
            const int row0 = bm + wm * 32 + mt * 16 + r4;
            const int col  = bn + wn * 64 + nt * 8 + q * 2;
            const float b0 = bias[col], b1 = bias[col + 1];
            float d0 = acc[mt][nt][0] + b0;
            float d1 = acc[mt][nt][1] + b1;
            float d2 = acc[mt][nt][2] + b0;
            float d3 = acc[mt][nt][3] + b1;
            if (OUT == 0) {
                *reinterpret_cast<float2*>(Cf + (size_t)row0 * Ntot + col) =
                    make_float2(d0, d1);
                *reinterpret_cast<float2*>(Cf + (size_t)(row0 + 8) * Ntot + col) =
                    make_float2(d2, d3);
            } else {
                float t0 = tanhf(d0), t1 = tanhf(d1), t2 = tanhf(d2), t3 = tanhf(d3);
                __half h0 = __float2half_rn(t0), h1 = __float2half_rn(t1);
                __half h2 = __float2half_rn(t2), h3 = __float2half_rn(t3);
                __half2 hv01 = __halves2half2(h0, h1);
                __half2 hv23 = __halves2half2(h2, h3);
                __half2 lv01 = __halves2half2(
                    __float2half_rn(t0 - __half2float(h0)),
                    __float2half_rn(t1 - __half2float(h1)));
                __half2 lv23 = __halves2half2(
                    __float2half_rn(t2 - __half2float(h2)),
                    __float2half_rn(t3 - __half2float(h3)));
                *reinterpret_cast<__half2*>(Ch + (size_t)row0 * Ntot + col) = hv01;
                *reinterpret_cast<__half2*>(Ch + (size_t)(row0 + 8) * Ntot + col) = hv23;
                *reinterpret_cast<__half2*>(Cl + (size_t)row0 * Ntot + col) = lv01;
                *reinterpret_cast<__half2*>(Cl + (size_t)(row0 + 8) * Ntot + col) = lv23;
            }
        }
    }
}

// ---------------------------------------------------------------------------
// GEMM1 (fp32, K=70): h1 = tanh(states @ W1 + b1), split-stored as fp16 hi/lo
// ---------------------------------------------------------------------------
__global__ __launch_bounds__(256, 2)
void sgemm_split(const float* __restrict__ A, const float* __restrict__ B,
                 const float* __restrict__ bias,
                 __half* __restrict__ Chh, __half* __restrict__ Cll,
                 int M, int N, int K)
{
    __shared__ float As[8][128];
    __shared__ float Bs[8][128];

    const int tid = threadIdx.x;
    const int bm = blockIdx.y * 128, bn = blockIdx.x * 128;
    const int tm = (tid >> 4) * 8, tn = (tid & 15) * 8;

    float acc[8][8];
#pragma unroll
    for (int i = 0; i < 8; i++)
#pragma unroll
        for (int j = 0; j < 8; j++) acc[i][j] = 0.0f;

    const int aM = (tid * 4) >> 3, aK = (tid * 4) & 7;
    const int bK = (tid * 4) >> 7, bN = (tid * 4) & 127;

    for (int k0 = 0; k0 < K; k0 += 8) {
#pragma unroll
        for (int i = 0; i < 4; i++) {
            int kk = aK + i;
            float v = 0.0f;
            if (k0 + kk < K) v = A[(size_t)(bm + aM) * K + k0 + kk];
            As[kk][aM] = v;
        }
        if (k0 + bK < K)
            *reinterpret_cast<float4*>(&Bs[bK][bN]) =
                *reinterpret_cast<const float4*>(&B[(size_t)(k0 + bK) * N + bn + bN]);
        else
            *reinterpret_cast<float4*>(&Bs[bK][bN]) = make_float4(0.f, 0.f, 0.f, 0.f);
        __syncthreads();

#pragma unroll
        for (int k = 0; k < 8; k++) {
            float a[8], b[8];
#pragma unroll
            for (int h = 0; h < 2; h++) {
                float4 t = *reinterpret_cast<const float4*>(&As[k][tm + h * 4]);
                a[h*4] = t.x; a[h*4+1] = t.y; a[h*4+2] = t.z; a[h*4+3] = t.w;
            }
#pragma unroll
            for (int h = 0; h < 2; h++) {
                float4 t = *reinterpret_cast<const float4*>(&Bs[k][tn + h * 4]);
                b[h*4] = t.x; b[h*4+1] = t.y; b[h*4+2] = t.z; b[h*4+3] = t.w;
            }
#pragma unroll
            for (int i = 0; i < 8; i++)
#pragma unroll
                for (int j = 0; j < 8; j++)
                    acc[i][j] = fmaf(a[i], b[j], acc[i][j]);
        }
        __syncthreads();
    }

#pragma unroll
    for (int i = 0; i < 8; i++) {
        union { uint4 u; __half h[8]; } H, L;
#pragma unroll
        for (int j = 0; j < 8; j++) {
            float v = tanhf(acc[i][j] + bias[bn + tn + j]);
            __half hi = __float2half_rn(v);
            H.h[j] = hi;
            L.h[j] = __float2half_rn(v - __half2float(hi));
        }
        *reinterpret_cast<uint4*>(&Chh[(size_t)(bm + tm + i) * N + bn + tn]) = H.u;
        *reinterpret_cast<uint4*>(&Cll[(size_t)(bm + tm + i) * N + bn + tn]) = L.u;
    }
}

// ---------------------------------------------------------------------------
// Weight prep: W[K,N] fp32 -> Wt [N,K] fp16 (transpose + round)
// ---------------------------------------------------------------------------
__global__ void transpose_half(const float* __restrict__ W,
                               __half* __restrict__ T, int K, int N)
{
    __shared__ float t[32][33];
    const int k0 = blockIdx.x * 32, n0 = blockIdx.y * 32;
    const int tx = threadIdx.x, ty = threadIdx.y;
    for (int j = ty; j < 32; j += 8)
        t[j][tx] = W[(size_t)(k0 + j) * N + n0 + tx];
    __syncthreads();
    for (int j = ty; j < 32; j += 8)
        T[(size_t)(n0 + j) * K + k0 + tx] = __float2half_rn(t[tx][j]);
}

// ---------------------------------------------------------------------------
// In-place masked softmax
// ---------------------------------------------------------------------------
__global__ __launch_bounds__(256)
void masked_softmax(float* __restrict__ out, const float* __restrict__ states)
{
    const int row = blockIdx.x;
    const int tid = threadIdx.x;

    __shared__ float sred[32];
    __shared__ int scap[6];

    if (tid < 6) scap[tid] = (int)floorf(states[(size_t)row * SDIM + NS + tid]);
    __syncthreads();

    const int c0 = scap[0], c1 = scap[1], c2 = scap[2];
    const int c3 = scap[3], c4 = scap[4], c5 = scap[5];

    float* rowp = out + (size_t)row * NACT;
    float vals[16];
    float mx = -INFINITY;

#pragma unroll
    for (int i = 0; i < 16; i++) {
        int a = tid + i * 256;
        float v = rowp[a];
        bool feas = (((a >> 10) & 3) <= c0) && (((a >> 8) & 3) <= c1) &&
                    (((a >> 6) & 3) <= c2) && (((a >> 4) & 3) <= c3) &&
                    (((a >> 2) & 3) <= c4) && (((a) & 3) <= c5);
        if (!feas) v += LOG_EPS;
        vals[i] = v;
        mx = fmaxf(mx, v);
    }

#pragma unroll
    for (int o = 16; o > 0; o >>= 1) mx = fmaxf(mx, __shfl_xor_sync(0xffffffffu, mx, o));
    if ((tid & 31) == 0) sred[tid >> 5] = mx;
    __syncthreads();
    if (tid < 32) {
        float m = (tid < 8) ? sred[tid] : -INFINITY;
#pragma unroll
        for (int o = 4; o > 0; o >>= 1) m = fmaxf(m, __shfl_xor_sync(0xffffffffu, m, o));
        if (tid == 0) sred[0] = m;
    }
    __syncthreads();
    mx = sred[0];
    __syncthreads();

    float sum = 0.0f;
#pragma unroll
    for (int i = 0; i < 16; i++) { vals[i] = expf(vals[i] - mx); sum += vals[i]; }

#pragma unroll
    for (int o = 16; o > 0; o >>= 1) sum += __shfl_xor_sync(0xffffffffu, sum, o);
    if ((tid & 31) == 0) sred[tid >> 5] = sum;
    __syncthreads();
    if (tid < 32) {
        float s = (tid < 8) ? sred[tid] : 0.0f;
#pragma unroll
        for (int o = 4; o > 0; o >>= 1) s += __shfl_xor_sync(0xffffffffu, s, o);
        if (tid == 0) sred[0] = s;
    }
    __syncthreads();
    const float inv = 1.0f / sred[0];

#pragma unroll
    for (int i = 0; i < 16; i++)
        rowp[tid + i * 256] = vals[i] * inv;
}

// ---------------------------------------------------------------------------
extern "C" void kernel_launch(void* const* d_in, const int* in_sizes, int n_in,
                              void* d_out, int out_size)
{
    const float* states = (const float*)d_in[0];
    const float* W1     = (const float*)d_in[1];
    const float* b1     = (const float*)d_in[2];
    const float* W2     = (const float*)d_in[3];
    const float* b2     = (const float*)d_in[4];
    const float* Wh     = (const float*)d_in[5];
    const float* bh     = (const float*)d_in[6];
    float* out = (float*)d_out;

    __half *h1h, *h1l, *h2h, *h2l, *W2T, *WhT;
    cudaGetSymbolAddress((void**)&h1h, g_h1h);
    cudaGetSymbolAddress((void**)&h1l, g_h1l);
    cudaGetSymbolAddress((void**)&h2h, g_h2h);
    cudaGetSymbolAddress((void**)&h2l, g_h2l);
    cudaGetSymbolAddress((void**)&W2T, g_W2T);
    cudaGetSymbolAddress((void**)&WhT, g_WhT);

    cudaFuncSetAttribute(hmma_gemm<0>, cudaFuncAttributeMaxDynamicSharedMemorySize, HMMA_SMEM);
    cudaFuncSetAttribute(hmma_gemm<1>, cudaFuncAttributeMaxDynamicSharedMemorySize, HMMA_SMEM);

    // weight prep (transpose + fp16 round)
    transpose_half<<<dim3(HID / 32, HID / 32), dim3(32, 8)>>>(W2, W2T, HID, HID);
    transpose_half<<<dim3(HID / 32, NACT / 32), dim3(32, 8)>>>(Wh, WhT, HID, NACT);

    // layer 1 (fp32 SGEMM, K=70) -> h1 split fp16
    sgemm_split<<<dim3(HID / 128, BATCH / 128), 256>>>(states, W1, b1, h1h, h1l,
                                                       BATCH, HID, SDIM);
    // layer 2 (HMMA fp16 2-term) -> h2 split fp16
    hmma_gemm<1><<<dim3(HID / 128, BATCH / 128), 256, HMMA_SMEM>>>(
        h1h, h1l, W2T, b2, nullptr, h2h, h2l, HID, HID);
    // head (HMMA fp16 2-term) -> logits fp32 straight into d_out
    hmma_gemm<0><<<dim3(NACT / 128, BATCH / 128), 256, HMMA_SMEM>>>(
        h2h, h2l, WhT, bh, out, nullptr, nullptr, HID, NACT);
    // masked softmax in place
    masked_softmax<<<BATCH, 256>>>(out, states);
}

// round 6
// speedup vs baseline: 2.3073x; 1.4227x over previous
#include <cuda_runtime.h>
#include <cuda_fp16.h>
#include <math.h>
#include <stdint.h>

// Problem constants
#define BATCH 8192
#define SDIM  70
#define NS    64
#define HID   1024
#define NACT  4096
#define LOG_EPS (-20.723265836946407f)   // logf(1e-9f)

// ---------------------------------------------------------------------------
// Scratch (allocation-free __device__ globals)
// ---------------------------------------------------------------------------
__device__ __align__(16) __half g_h1[BATCH * HID];
__device__ __align__(16) __half g_h2[BATCH * HID];
__device__ __align__(16) __half g_W2T[HID * HID];
__device__ __align__(16) __half g_WhT[NACT * HID];

// ---------------------------------------------------------------------------
// Helpers (plain sm_80+ PTX only — nothing sm_103a-conditional)
// ---------------------------------------------------------------------------
__device__ __forceinline__ uint32_t smem_u32(const void* p) {
    uint32_t a;
    asm("{ .reg .u64 t; cvta.to.shared.u64 t, %1; cvt.u32.u64 %0, t; }" : "=r"(a) : "l"(p));
    return a;
}

__device__ __forceinline__ void cp_async16(uint32_t saddr, const void* gaddr) {
    asm volatile("cp.async.cg.shared.global [%0], [%1], 16;" :: "r"(saddr), "l"(gaddr));
}
#define CP_COMMIT()  asm volatile("cp.async.commit_group;" ::: "memory")
#define CP_WAIT(n)   asm volatile("cp.async.wait_group %0;" :: "n"(n) : "memory")

__device__ __forceinline__ void ldsm_x4(uint32_t* r, uint32_t addr) {
    asm volatile("ldmatrix.sync.aligned.m8n8.x4.shared.b16 {%0,%1,%2,%3}, [%4];"
        : "=r"(r[0]), "=r"(r[1]), "=r"(r[2]), "=r"(r[3]) : "r"(addr));
}

__device__ __forceinline__ void mma16816(float* d, const uint32_t* a, const uint32_t* b) {
    asm volatile("mma.sync.aligned.m16n8k16.row.col.f32.f16.f16.f32 "
        "{%0,%1,%2,%3}, {%4,%5,%6,%7}, {%8,%9}, {%0,%1,%2,%3};"
        : "+f"(d[0]), "+f"(d[1]), "+f"(d[2]), "+f"(d[3])
        : "r"(a[0]), "r"(a[1]), "r"(a[2]), "r"(a[3]), "r"(b[0]), "r"(b[1]));
}

// ---------------------------------------------------------------------------
// HMMA GEMM (single fp16):
//   C[M,Ntot] = act( A[M,K] @ B^T + bias ),  A fp16 [M,K], B fp16 [Ntot,K].
// CTA tile 128x128, K-tile 64, 8 warps in 4(m) x 2(n); warp tile 32 x 64.
// 3-stage cp.async ring, XOR-8 swizzled 128B smem rows (R3/R5-verified layout).
// ---------------------------------------------------------------------------
#define KT 64
#define A_BYTES  16384                 // 128 rows x 128 B
#define STAGE_BYTES (2 * A_BYTES)      // A + B = 32768
#define NSTAGE 3
#define HMMA_SMEM (NSTAGE * STAGE_BYTES)   // 98304

template <int OUT>
__global__ __launch_bounds__(256, 2)
void hmma_gemm(const __half* __restrict__ A, const __half* __restrict__ B,
               const float* __restrict__ bias,
               float* __restrict__ Cf, __half* __restrict__ Ch,
               int K, int Ntot)
{
    extern __shared__ char smem_raw[];
    const uint32_t sbase = smem_u32(smem_raw);

    const int tid  = threadIdx.x;
    const int lane = tid & 31;
    const int wid  = tid >> 5;
    const int wm   = wid & 3;          // 4 warps along M (32 rows each)
    const int wn   = wid >> 2;         // 2 warps along N (64 cols each)
    const int bm   = blockIdx.y * 128;
    const int bn   = blockIdx.x * 128;
    const int nst  = K / KT;           // 16 for K=1024

    float acc[2][8][4];
#pragma unroll
    for (int i = 0; i < 2; i++)
#pragma unroll
        for (int j = 0; j < 8; j++)
#pragma unroll
            for (int q = 0; q < 4; q++) acc[i][j][q] = 0.0f;

    // ---- stage loader: 2 x 1024 16B chunks (A, B), 8 per thread -------------
    auto load_stage = [&](int i, int s) {
        const int kl = i * KT;
        const uint32_t sA = sbase + s * STAGE_BYTES;
        const uint32_t sB = sA + A_BYTES;
#pragma unroll
        for (int p = 0; p < 4; p++) {
            const int idx = p * 256 + tid;
            const int r = idx >> 3, c = idx & 7;
            const uint32_t so = r * 128 + ((c ^ (r & 7)) << 4);
            cp_async16(sA + so, A + (size_t)(bm + r) * K + kl + c * 8);
            cp_async16(sB + so, B + (size_t)(bn + r) * K + kl + c * 8);
        }
        CP_COMMIT();
    };

    load_stage(0, 0);
    load_stage(1, 1);

    for (int i = 0; i < nst; i++) {
        const int s = i % NSTAGE;
        CP_WAIT(1);
        __syncthreads();

        if (i + 2 < nst) load_stage(i + 2, (i + 2) % NSTAGE);

        const uint32_t sA = sbase + s * STAGE_BYTES;
        const uint32_t sB = sA + A_BYTES;

#pragma unroll
        for (int ks = 0; ks < KT / 16; ks++) {
            // A fragments: 2 m16 tiles
            uint32_t a[2][4];
#pragma unroll
            for (int mt = 0; mt < 2; mt++) {
                const int row = wm * 32 + mt * 16 + (lane & 15);
                const int ch  = ks * 2 + (lane >> 4);
                ldsm_x4(a[mt], sA + row * 128 + ((ch ^ (row & 7)) << 4));
            }
            // B fragments: 4 x ldmatrix.x4
            uint32_t b[4][4];
#pragma unroll
            for (int np = 0; np < 4; np++) {
                const int nrow = wn * 64 + np * 16 + ((lane >> 4) << 3) + (lane & 7);
                const int ch   = ks * 2 + ((lane >> 3) & 1);
                ldsm_x4(b[np], sB + nrow * 128 + ((ch ^ (nrow & 7)) << 4));
            }
#pragma unroll
            for (int mt = 0; mt < 2; mt++)
#pragma unroll
                for (int np = 0; np < 4; np++) {
                    mma16816(acc[mt][np * 2 + 0], a[mt], &b[np][0]);
                    mma16816(acc[mt][np * 2 + 1], a[mt], &b[np][2]);
                }
        }
    }

    // ---- epilogue ----
    const int q  = lane & 3;
    const int r4 = lane >> 2;
#pragma unroll
    for (int mt = 0; mt < 2; mt++) {
#pragma unroll
        for (int nt = 0; nt < 8; nt++) {
            const int row0 = bm + wm * 32 + mt * 16 + r4;
            const int col  = bn + wn * 64 + nt * 8 + q * 2;
            const float b0 = bias[col], b1 = bias[col + 1];
            float d0 = acc[mt][nt][0] + b0;
            float d1 = acc[mt][nt][1] + b1;
            float d2 = acc[mt][nt][2] + b0;
            float d3 = acc[mt][nt][3] + b1;
            if (OUT == 0) {
                *reinterpret_cast<float2*>(Cf + (size_t)row0 * Ntot + col) =
                    make_float2(d0, d1);
                *reinterpret_cast<float2*>(Cf + (size_t)(row0 + 8) * Ntot + col) =
                    make_float2(d2, d3);
            } else {
                *reinterpret_cast<__half2*>(Ch + (size_t)row0 * Ntot + col) =
                    __halves2half2(__float2half_rn(tanhf(d0)), __float2half_rn(tanhf(d1)));
                *reinterpret_cast<__half2*>(Ch + (size_t)(row0 + 8) * Ntot + col) =
                    __halves2half2(__float2half_rn(tanhf(d2)), __float2half_rn(tanhf(d3)));
            }
        }
    }
}

// ---------------------------------------------------------------------------
// GEMM1 (fp32, K=70): h1 = tanh(states @ W1 + b1) stored as fp16
// ---------------------------------------------------------------------------
__global__ __launch_bounds__(256, 2)
void sgemm_h(const float* __restrict__ A, const float* __restrict__ B,
             const float* __restrict__ bias, __half* __restrict__ C,
             int M, int N, int K)
{
    __shared__ float As[8][128];
    __shared__ float Bs[8][128];

    const int tid = threadIdx.x;
    const int bm = blockIdx.y * 128, bn = blockIdx.x * 128;
    const int tm = (tid >> 4) * 8, tn = (tid & 15) * 8;

    float acc[8][8];
#pragma unroll
    for (int i = 0; i < 8; i++)
#pragma unroll
        for (int j = 0; j < 8; j++) acc[i][j] = 0.0f;

    const int aM = (tid * 4) >> 3, aK = (tid * 4) & 7;
    const int bK = (tid * 4) >> 7, bN = (tid * 4) & 127;

    for (int k0 = 0; k0 < K; k0 += 8) {
#pragma unroll
        for (int i = 0; i < 4; i++) {
            int kk = aK + i;
            float v = 0.0f;
            if (k0 + kk < K) v = A[(size_t)(bm + aM) * K + k0 + kk];
            As[kk][aM] = v;
        }
        if (k0 + bK < K)
            *reinterpret_cast<float4*>(&Bs[bK][bN]) =
                *reinterpret_cast<const float4*>(&B[(size_t)(k0 + bK) * N + bn + bN]);
        else
            *reinterpret_cast<float4*>(&Bs[bK][bN]) = make_float4(0.f, 0.f, 0.f, 0.f);
        __syncthreads();

#pragma unroll
        for (int k = 0; k < 8; k++) {
            float a[8], b[8];
#pragma unroll
            for (int h = 0; h < 2; h++) {
                float4 t = *reinterpret_cast<const float4*>(&As[k][tm + h * 4]);
                a[h*4] = t.x; a[h*4+1] = t.y; a[h*4+2] = t.z; a[h*4+3] = t.w;
            }
#pragma unroll
            for (int h = 0; h < 2; h++) {
                float4 t = *reinterpret_cast<const float4*>(&Bs[k][tn + h * 4]);
                b[h*4] = t.x; b[h*4+1] = t.y; b[h*4+2] = t.z; b[h*4+3] = t.w;
            }
#pragma unroll
            for (int i = 0; i < 8; i++)
#pragma unroll
                for (int j = 0; j < 8; j++)
                    acc[i][j] = fmaf(a[i], b[j], acc[i][j]);
        }
        __syncthreads();
    }

#pragma unroll
    for (int i = 0; i < 8; i++) {
        union { uint4 u; __half h[8]; } H;
#pragma unroll
        for (int j = 0; j < 8; j++)
            H.h[j] = __float2half_rn(tanhf(acc[i][j] + bias[bn + tn + j]));
        *reinterpret_cast<uint4*>(&C[(size_t)(bm + tm + i) * N + bn + tn]) = H.u;
    }
}

// ---------------------------------------------------------------------------
// Weight prep: W[K,N] fp32 -> Wt [N,K] fp16 (transpose + round)
// ---------------------------------------------------------------------------
__global__ void transpose_half(const float* __restrict__ W,
                               __half* __restrict__ T, int K, int N)
{
    __shared__ float t[32][33];
    const int k0 = blockIdx.x * 32, n0 = blockIdx.y * 32;
    const int tx = threadIdx.x, ty = threadIdx.y;
    for (int j = ty; j < 32; j += 8)
        t[j][tx] = W[(size_t)(k0 + j) * N + n0 + tx];
    __syncthreads();
    for (int j = ty; j < 32; j += 8)
        T[(size_t)(n0 + j) * K + k0 + tx] = __float2half_rn(t[tx][j]);
}

// ---------------------------------------------------------------------------
// In-place masked softmax
// ---------------------------------------------------------------------------
__global__ __launch_bounds__(256)
void masked_softmax(float* __restrict__ out, const float* __restrict__ states)
{
    const int row = blockIdx.x;
    const int tid = threadIdx.x;

    __shared__ float sred[32];
    __shared__ int scap[6];

    if (tid < 6) scap[tid] = (int)floorf(states[(size_t)row * SDIM + NS + tid]);
    __syncthreads();

    const int c0 = scap[0], c1 = scap[1], c2 = scap[2];
    const int c3 = scap[3], c4 = scap[4], c5 = scap[5];

    float* rowp = out + (size_t)row * NACT;
    float vals[16];
    float mx = -INFINITY;

#pragma unroll
    for (int i = 0; i < 16; i++) {
        int a = tid + i * 256;
        float v = rowp[a];
        bool feas = (((a >> 10) & 3) <= c0) && (((a >> 8) & 3) <= c1) &&
                    (((a >> 6) & 3) <= c2) && (((a >> 4) & 3) <= c3) &&
                    (((a >> 2) & 3) <= c4) && (((a) & 3) <= c5);
        if (!feas) v += LOG_EPS;
        vals[i] = v;
        mx = fmaxf(mx, v);
    }

#pragma unroll
    for (int o = 16; o > 0; o >>= 1) mx = fmaxf(mx, __shfl_xor_sync(0xffffffffu, mx, o));
    if ((tid & 31) == 0) sred[tid >> 5] = mx;
    __syncthreads();
    if (tid < 32) {
        float m = (tid < 8) ? sred[tid] : -INFINITY;
#pragma unroll
        for (int o = 4; o > 0; o >>= 1) m = fmaxf(m, __shfl_xor_sync(0xffffffffu, m, o));
        if (tid == 0) sred[0] = m;
    }
    __syncthreads();
    mx = sred[0];
    __syncthreads();

    float sum = 0.0f;
#pragma unroll
    for (int i = 0; i < 16; i++) { vals[i] = expf(vals[i] - mx); sum += vals[i]; }

#pragma unroll
    for (int o = 16; o > 0; o >>= 1) sum += __shfl_xor_sync(0xffffffffu, sum, o);
    if ((tid & 31) == 0) sred[tid >> 5] = sum;
    __syncthreads();
    if (tid < 32) {
        float s = (tid < 8) ? sred[tid] : 0.0f;
#pragma unroll
        for (int o = 4; o > 0; o >>= 1) s += __shfl_xor_sync(0xffffffffu, s, o);
        if (tid == 0) sred[0] = s;
    }
    __syncthreads();
    const float inv = 1.0f / sred[0];

#pragma unroll
    for (int i = 0; i < 16; i++)
        rowp[tid + i * 256] = vals[i] * inv;
}

// ---------------------------------------------------------------------------
extern "C" void kernel_launch(void* const* d_in, const int* in_sizes, int n_in,
                              void* d_out, int out_size)
{
    const float* states = (const float*)d_in[0];
    const float* W1     = (const float*)d_in[1];
    const float* b1     = (const float*)d_in[2];
    const float* W2     = (const float*)d_in[3];
    const float* b2     = (const float*)d_in[4];
    const float* Wh     = (const float*)d_in[5];
    const float* bh     = (const float*)d_in[6];
    float* out = (float*)d_out;

    __half *h1, *h2, *W2T, *WhT;
    cudaGetSymbolAddress((void**)&h1,  g_h1);
    cudaGetSymbolAddress((void**)&h2,  g_h2);
    cudaGetSymbolAddress((void**)&W2T, g_W2T);
    cudaGetSymbolAddress((void**)&WhT, g_WhT);

    cudaFuncSetAttribute(hmma_gemm<0>, cudaFuncAttributeMaxDynamicSharedMemorySize, HMMA_SMEM);
    cudaFuncSetAttribute(hmma_gemm<1>, cudaFuncAttributeMaxDynamicSharedMemorySize, HMMA_SMEM);

    // weight prep (transpose + fp16 round)
    transpose_half<<<dim3(HID / 32, HID / 32), dim3(32, 8)>>>(W2, W2T, HID, HID);
    transpose_half<<<dim3(HID / 32, NACT / 32), dim3(32, 8)>>>(Wh, WhT, HID, NACT);

    // layer 1 (fp32 SGEMM, K=70) -> h1 fp16
    sgemm_h<<<dim3(HID / 128, BATCH / 128), 256>>>(states, W1, b1, h1,
                                                   BATCH, HID, SDIM);
    // layer 2 (HMMA fp16) -> h2 fp16
    hmma_gemm<1><<<dim3(HID / 128, BATCH / 128), 256, HMMA_SMEM>>>(
        h1, W2T, b2, nullptr, h2, HID, HID);
    // head (HMMA fp16) -> logits fp32 straight into d_out
    hmma_gemm<0><<<dim3(NACT / 128, BATCH / 128), 256, HMMA_SMEM>>>(
        h2, WhT, bh, out, nullptr, HID, NACT);
    // masked softmax in place
    masked_softmax<<<BATCH, 256>>>(out, states);
}

// round 7
// speedup vs baseline: 2.3648x; 1.0249x over previous
#include <cuda_runtime.h>
#include <cuda_fp16.h>
#include <math.h>
#include <stdint.h>

// Problem constants
#define BATCH 8192
#define SDIM  70
#define NS    64
#define HID   1024
#define NACT  4096
#define LOG_EPS (-20.723265836946407f)   // logf(1e-9f)

// ---------------------------------------------------------------------------
// Scratch (allocation-free __device__ globals)
// ---------------------------------------------------------------------------
__device__ __align__(16) __half g_h1[BATCH * HID];
__device__ __align__(16) __half g_h2[BATCH * HID];
__device__ __align__(16) __half g_W2T[HID * HID];
__device__ __align__(16) __half g_WhT[NACT * HID];

// ---------------------------------------------------------------------------
// Helpers (plain sm_80+ PTX only — nothing sm_103a-conditional)
// ---------------------------------------------------------------------------
__device__ __forceinline__ uint32_t smem_u32(const void* p) {
    uint32_t a;
    asm("{ .reg .u64 t; cvta.to.shared.u64 t, %1; cvt.u32.u64 %0, t; }" : "=r"(a) : "l"(p));
    return a;
}

__device__ __forceinline__ void cp_async16(uint32_t saddr, const void* gaddr) {
    asm volatile("cp.async.cg.shared.global [%0], [%1], 16;" :: "r"(saddr), "l"(gaddr));
}
#define CP_COMMIT()  asm volatile("cp.async.commit_group;" ::: "memory")
#define CP_WAIT(n)   asm volatile("cp.async.wait_group %0;" :: "n"(n) : "memory")

__device__ __forceinline__ void ldsm_x4(uint32_t* r, uint32_t addr) {
    asm volatile("ldmatrix.sync.aligned.m8n8.x4.shared.b16 {%0,%1,%2,%3}, [%4];"
        : "=r"(r[0]), "=r"(r[1]), "=r"(r[2]), "=r"(r[3]) : "r"(addr));
}

__device__ __forceinline__ void mma16816(float* d, const uint32_t* a, const uint32_t* b) {
    asm volatile("mma.sync.aligned.m16n8k16.row.col.f32.f16.f16.f32 "
        "{%0,%1,%2,%3}, {%4,%5,%6,%7}, {%8,%9}, {%0,%1,%2,%3};"
        : "+f"(d[0]), "+f"(d[1]), "+f"(d[2]), "+f"(d[3])
        : "r"(a[0]), "r"(a[1]), "r"(a[2]), "r"(a[3]), "r"(b[0]), "r"(b[1]));
}

// ---------------------------------------------------------------------------
// HMMA GEMM (single fp16):
//   C[M,Ntot] = act( A[M,K] @ B^T + bias ),  A fp16 [M,K], B fp16 [Ntot,K].
// CTA tile 128x128, K-tile 64, 8 warps in 4(m) x 2(n); warp tile 32 x 64.
// 2-stage cp.async double buffer (R5-proven structure: stage = i & 1,
// compile-time offsets, load after compute). XOR-8 swizzled 128B smem rows.
// ---------------------------------------------------------------------------
#define KT 64
#define A_BYTES  16384                 // 128 rows x 128 B
#define STAGE_BYTES (2 * A_BYTES)      // A + B = 32768
#define HMMA_SMEM (2 * STAGE_BYTES)    // 65536

template <int OUT>
__global__ __launch_bounds__(256, 2)
void hmma_gemm(const __half* __restrict__ A, const __half* __restrict__ B,
               const float* __restrict__ bias,
               float* __restrict__ Cf, __half* __restrict__ Ch,
               int K, int Ntot)
{
    extern __shared__ char smem_raw[];
    const uint32_t sbase = smem_u32(smem_raw);

    const int tid  = threadIdx.x;
    const int lane = tid & 31;
    const int wid  = tid >> 5;
    const int wm   = wid & 3;          // 4 warps along M (32 rows each)
    const int wn   = wid >> 2;         // 2 warps along N (64 cols each)
    const int bm   = blockIdx.y * 128;
    const int bn   = blockIdx.x * 128;
    const int nst  = K / KT;           // 16 for K=1024

    float acc[2][8][4];
#pragma unroll
    for (int i = 0; i < 2; i++)
#pragma unroll
        for (int j = 0; j < 8; j++)
#pragma unroll
            for (int q = 0; q < 4; q++) acc[i][j][q] = 0.0f;

    // ---- stage loader: 2 x 1024 16B chunks (A, B), 8 per thread -------------
    auto load_stage = [&](int i, int s) {
        const int kl = i * KT;
        const uint32_t sA = sbase + s * STAGE_BYTES;
        const uint32_t sB = sA + A_BYTES;
#pragma unroll
        for (int p = 0; p < 4; p++) {
            const int idx = p * 256 + tid;
            const int r = idx >> 3, c = idx & 7;
            const uint32_t so = r * 128 + ((c ^ (r & 7)) << 4);
            cp_async16(sA + so, A + (size_t)(bm + r) * K + kl + c * 8);
            cp_async16(sB + so, B + (size_t)(bn + r) * K + kl + c * 8);
        }
        CP_COMMIT();
    };

    load_stage(0, 0);
    load_stage(1, 1);

    for (int i = 0; i < nst; i++) {
        const int s = i & 1;
        if (i + 1 < nst) { CP_WAIT(1); } else { CP_WAIT(0); }
        __syncthreads();

        const uint32_t sA = sbase + s * STAGE_BYTES;
        const uint32_t sB = sA + A_BYTES;

#pragma unroll
        for (int ks = 0; ks < KT / 16; ks++) {
            // A fragments: 2 m16 tiles
            uint32_t a[2][4];
#pragma unroll
            for (int mt = 0; mt < 2; mt++) {
                const int row = wm * 32 + mt * 16 + (lane & 15);
                const int ch  = ks * 2 + (lane >> 4);
                ldsm_x4(a[mt], sA + row * 128 + ((ch ^ (row & 7)) << 4));
            }
            // B fragments: 4 x ldmatrix.x4
            uint32_t b[4][4];
#pragma unroll
            for (int np = 0; np < 4; np++) {
                const int nrow = wn * 64 + np * 16 + ((lane >> 4) << 3) + (lane & 7);
                const int ch   = ks * 2 + ((lane >> 3) & 1);
                ldsm_x4(b[np], sB + nrow * 128 + ((ch ^ (nrow & 7)) << 4));
            }
#pragma unroll
            for (int mt = 0; mt < 2; mt++)
#pragma unroll
                for (int np = 0; np < 4; np++) {
                    mma16816(acc[mt][np * 2 + 0], a[mt], &b[np][0]);
                    mma16816(acc[mt][np * 2 + 1], a[mt], &b[np][2]);
                }
        }
        __syncthreads();
        if (i + 2 < nst) load_stage(i + 2, s);
    }

    // ---- epilogue ----
    const int q  = lane & 3;
    const int r4 = lane >> 2;
#pragma unroll
    for (int mt = 0; mt < 2; mt++) {
#pragma unroll
        for (int nt = 0; nt < 8; nt++) {
            const int row0 = bm + wm * 32 + mt * 16 + r4;
            const int col  = bn + wn * 64 + nt * 8 + q * 2;
            const float b0 = bias[col], b1 = bias[col + 1];
            float d0 = acc[mt][nt][0] + b0;
            float d1 = acc[mt][nt][1] + b1;
            float d2 = acc[mt][nt][2] + b0;
            float d3 = acc[mt][nt][3] + b1;
            if (OUT == 0) {
                *reinterpret_cast<float2*>(Cf + (size_t)row0 * Ntot + col) =
                    make_float2(d0, d1);
                *reinterpret_cast<float2*>(Cf + (size_t)(row0 + 8) * Ntot + col) =
                    make_float2(d2, d3);
            } else {
                *reinterpret_cast<__half2*>(Ch + (size_t)row0 * Ntot + col) =
                    __halves2half2(__float2half_rn(tanhf(d0)), __float2half_rn(tanhf(d1)));
                *reinterpret_cast<__half2*>(Ch + (size_t)(row0 + 8) * Ntot + col) =
                    __halves2half2(__float2half_rn(tanhf(d2)), __float2half_rn(tanhf(d3)));
            }
        }
    }
}

// ---------------------------------------------------------------------------
// GEMM1 (fp32, K=70): h1 = tanh(states @ W1 + b1) stored as fp16
// ---------------------------------------------------------------------------
__global__ __launch_bounds__(256, 2)
void sgemm_h(const float* __restrict__ A, const float* __restrict__ B,
             const float* __restrict__ bias, __half* __restrict__ C,
             int M, int N, int K)
{
    __shared__ float As[8][128];
    __shared__ float Bs[8][128];

    const int tid = threadIdx.x;
    const int bm = blockIdx.y * 128, bn = blockIdx.x * 128;
    const int tm = (tid >> 4) * 8, tn = (tid & 15) * 8;

    float acc[8][8];
#pragma unroll
    for (int i = 0; i < 8; i++)
#pragma unroll
        for (int j = 0; j < 8; j++) acc[i][j] = 0.0f;

    const int aM = (tid * 4) >> 3, aK = (tid * 4) & 7;
    const int bK = (tid * 4) >> 7, bN = (tid * 4) & 127;

    for (int k0 = 0; k0 < K; k0 += 8) {
#pragma unroll
        for (int i = 0; i < 4; i++) {
            int kk = aK + i;
            float v = 0.0f;
            if (k0 + kk < K) v = A[(size_t)(bm + aM) * K + k0 + kk];
            As[kk][aM] = v;
        }
        if (k0 + bK < K)
            *reinterpret_cast<float4*>(&Bs[bK][bN]) =
                *reinterpret_cast<const float4*>(&B[(size_t)(k0 + bK) * N + bn + bN]);
        else
            *reinterpret_cast<float4*>(&Bs[bK][bN]) = make_float4(0.f, 0.f, 0.f, 0.f);
        __syncthreads();

#pragma unroll
        for (int k = 0; k < 8; k++) {
            float a[8], b[8];
#pragma unroll
            for (int h = 0; h < 2; h++) {
                float4 t = *reinterpret_cast<const float4*>(&As[k][tm + h * 4]);
                a[h*4] = t.x; a[h*4+1] = t.y; a[h*4+2] = t.z; a[h*4+3] = t.w;
            }
#pragma unroll
            for (int h = 0; h < 2; h++) {
                float4 t = *reinterpret_cast<const float4*>(&Bs[k][tn + h * 4]);
                b[h*4] = t.x; b[h*4+1] = t.y; b[h*4+2] = t.z; b[h*4+3] = t.w;
            }
#pragma unroll
            for (int i = 0; i < 8; i++)
#pragma unroll
                for (int j = 0; j < 8; j++)
                    acc[i][j] = fmaf(a[i], b[j], acc[i][j]);
        }
        __syncthreads();
    }

#pragma unroll
    for (int i = 0; i < 8; i++) {
        union { uint4 u; __half h[8]; } H;
#pragma unroll
        for (int j = 0; j < 8; j++)
            H.h[j] = __float2half_rn(tanhf(acc[i][j] + bias[bn + tn + j]));
        *reinterpret_cast<uint4*>(&C[(size_t)(bm + tm + i) * N + bn + tn]) = H.u;
    }
}

// ---------------------------------------------------------------------------
// Weight prep: W[K,N] fp32 -> Wt [N,K] fp16 (transpose + round)
// ---------------------------------------------------------------------------
__global__ void transpose_half(const float* __restrict__ W,
                               __half* __restrict__ T, int K, int N)
{
    __shared__ float t[32][33];
    const int k0 = blockIdx.x * 32, n0 = blockIdx.y * 32;
    const int tx = threadIdx.x, ty = threadIdx.y;
    for (int j = ty; j < 32; j += 8)
        t[j][tx] = W[(size_t)(k0 + j) * N + n0 + tx];
    __syncthreads();
    for (int j = ty; j < 32; j += 8)
        T[(size_t)(n0 + j) * K + k0 + tx] = __float2half_rn(t[tx][j]);
}

// ---------------------------------------------------------------------------
// In-place masked softmax — float4 vectorized (16 consecutive actions/thread)
// ---------------------------------------------------------------------------
__global__ __launch_bounds__(256)
void masked_softmax(float* __restrict__ out, const float* __restrict__ states)
{
    const int row = blockIdx.x;
    const int tid = threadIdx.x;

    __shared__ float sred[32];
    __shared__ int scap[6];

    if (tid < 6) scap[tid] = (int)floorf(states[(size_t)row * SDIM + NS + tid]);
    __syncthreads();

    const int c0 = scap[0], c1 = scap[1], c2 = scap[2];
    const int c3 = scap[3], c4 = scap[4], c5 = scap[5];

    float* rowp = out + (size_t)row * NACT;
    const int base = tid * 16;

    float vals[16];
    float mx = -INFINITY;

#pragma unroll
    for (int v4i = 0; v4i < 4; v4i++) {
        float4 v = *reinterpret_cast<const float4*>(rowp + base + v4i * 4);
        float* vp = reinterpret_cast<float*>(&v);
#pragma unroll
        for (int c = 0; c < 4; c++) {
            const int a = base + v4i * 4 + c;
            bool feas = (((a >> 10) & 3) <= c0) && (((a >> 8) & 3) <= c1) &&
                        (((a >> 6) & 3) <= c2) && (((a >> 4) & 3) <= c3) &&
                        (((a >> 2) & 3) <= c4) && (((a) & 3) <= c5);
            float x = vp[c];
            if (!feas) x += LOG_EPS;
            vals[v4i * 4 + c] = x;
            mx = fmaxf(mx, x);
        }
    }

#pragma unroll
    for (int o = 16; o > 0; o >>= 1) mx = fmaxf(mx, __shfl_xor_sync(0xffffffffu, mx, o));
    if ((tid & 31) == 0) sred[tid >> 5] = mx;
    __syncthreads();
    if (tid < 32) {
        float m = (tid < 8) ? sred[tid] : -INFINITY;
#pragma unroll
        for (int o = 4; o > 0; o >>= 1) m = fmaxf(m, __shfl_xor_sync(0xffffffffu, m, o));
        if (tid == 0) sred[0] = m;
    }
    __syncthreads();
    mx = sred[0];
    __syncthreads();

    float sum = 0.0f;
#pragma unroll
    for (int i = 0; i < 16; i++) { vals[i] = expf(vals[i] - mx); sum += vals[i]; }

#pragma unroll
    for (int o = 16; o > 0; o >>= 1) sum += __shfl_xor_sync(0xffffffffu, sum, o);
    if ((tid & 31) == 0) sred[tid >> 5] = sum;
    __syncthreads();
    if (tid < 32) {
        float s = (tid < 8) ? sred[tid] : 0.0f;
#pragma unroll
        for (int o = 4; o > 0; o >>= 1) s += __shfl_xor_sync(0xffffffffu, s, o);
        if (tid == 0) sred[0] = s;
    }
    __syncthreads();
    const float inv = 1.0f / sred[0];

#pragma unroll
    for (int v4i = 0; v4i < 4; v4i++) {
        float4 o4;
        o4.x = vals[v4i * 4 + 0] * inv;
        o4.y = vals[v4i * 4 + 1] * inv;
        o4.z = vals[v4i * 4 + 2] * inv;
        o4.w = vals[v4i * 4 + 3] * inv;
        *reinterpret_cast<float4*>(rowp + base + v4i * 4) = o4;
    }
}

// ---------------------------------------------------------------------------
extern "C" void kernel_launch(void* const* d_in, const int* in_sizes, int n_in,
                              void* d_out, int out_size)
{
    const float* states = (const float*)d_in[0];
    const float* W1     = (const float*)d_in[1];
    const float* b1     = (const float*)d_in[2];
    const float* W2     = (const float*)d_in[3];
    const float* b2     = (const float*)d_in[4];
    const float* Wh     = (const float*)d_in[5];
    const float* bh     = (const float*)d_in[6];
    float* out = (float*)d_out;

    __half *h1, *h2, *W2T, *WhT;
    cudaGetSymbolAddress((void**)&h1,  g_h1);
    cudaGetSymbolAddress((void**)&h2,  g_h2);
    cudaGetSymbolAddress((void**)&W2T, g_W2T);
    cudaGetSymbolAddress((void**)&WhT, g_WhT);

    cudaFuncSetAttribute(hmma_gemm<0>, cudaFuncAttributeMaxDynamicSharedMemorySize, HMMA_SMEM);
    cudaFuncSetAttribute(hmma_gemm<1>, cudaFuncAttributeMaxDynamicSharedMemorySize, HMMA_SMEM);

    // weight prep (transpose + fp16 round)
    transpose_half<<<dim3(HID / 32, HID / 32), dim3(32, 8)>>>(W2, W2T, HID, HID);
    transpose_half<<<dim3(HID / 32, NACT / 32), dim3(32, 8)>>>(Wh, WhT, HID, NACT);

    // layer 1 (fp32 SGEMM, K=70) -> h1 fp16
    sgemm_h<<<dim3(HID / 128, BATCH / 128), 256>>>(states, W1, b1, h1,
                                                   BATCH, HID, SDIM);
    // layer 2 (HMMA fp16) -> h2 fp16
    hmma_gemm<1><<<dim3(HID / 128, BATCH / 128), 256, HMMA_SMEM>>>(
        h1, W2T, b2, nullptr, h2, HID, HID);
    // head (HMMA fp16) -> logits fp32 straight into d_out
    hmma_gemm<0><<<dim3(NACT / 128, BATCH / 128), 256, HMMA_SMEM>>>(
        h2, WhT, bh, out, nullptr, HID, NACT);
    // masked softmax in place
    masked_softmax<<<BATCH, 256>>>(out, states);
}

// round 8
// speedup vs baseline: 2.5185x; 1.0650x over previous
#include <cuda_runtime.h>
#include <cuda_fp16.h>
#include <math.h>
#include <stdint.h>

// Problem constants
#define BATCH 8192
#define SDIM  70
#define NS    64
#define HID   1024
#define NACT  4096
#define K1PAD 128                        // K=70 zero-padded for HMMA layer 1
#define LOG_EPS (-20.723265836946407f)   // logf(1e-9f)

// ---------------------------------------------------------------------------
// Scratch (allocation-free __device__ globals)
// ---------------------------------------------------------------------------
__device__ __align__(16) __half g_sp[BATCH * K1PAD];    // states fp16, K-padded
__device__ __align__(16) __half g_W1T[HID * K1PAD];     // W1^T fp16, K-padded
__device__ __align__(16) __half g_h1[BATCH * HID];
__device__ __align__(16) __half g_h2[BATCH * HID];
__device__ __align__(16) __half g_W2T[HID * HID];
__device__ __align__(16) __half g_WhT[NACT * HID];

// ---------------------------------------------------------------------------
// Helpers (plain sm_80+ PTX only — nothing sm_103a-conditional)
// ---------------------------------------------------------------------------
__device__ __forceinline__ uint32_t smem_u32(const void* p) {
    uint32_t a;
    asm("{ .reg .u64 t; cvta.to.shared.u64 t, %1; cvt.u32.u64 %0, t; }" : "=r"(a) : "l"(p));
    return a;
}

__device__ __forceinline__ void cp_async16(uint32_t saddr, const void* gaddr) {
    asm volatile("cp.async.cg.shared.global [%0], [%1], 16;" :: "r"(saddr), "l"(gaddr));
}
#define CP_COMMIT()  asm volatile("cp.async.commit_group;" ::: "memory")
#define CP_WAIT(n)   asm volatile("cp.async.wait_group %0;" :: "n"(n) : "memory")

__device__ __forceinline__ void ldsm_x4(uint32_t* r, uint32_t addr) {
    asm volatile("ldmatrix.sync.aligned.m8n8.x4.shared.b16 {%0,%1,%2,%3}, [%4];"
        : "=r"(r[0]), "=r"(r[1]), "=r"(r[2]), "=r"(r[3]) : "r"(addr));
}

__device__ __forceinline__ void mma16816(float* d, const uint32_t* a, const uint32_t* b) {
    asm volatile("mma.sync.aligned.m16n8k16.row.col.f32.f16.f16.f32 "
        "{%0,%1,%2,%3}, {%4,%5,%6,%7}, {%8,%9}, {%0,%1,%2,%3};"
        : "+f"(d[0]), "+f"(d[1]), "+f"(d[2]), "+f"(d[3])
        : "r"(a[0]), "r"(a[1]), "r"(a[2]), "r"(a[3]), "r"(b[0]), "r"(b[1]));
}

// ---------------------------------------------------------------------------
// HMMA GEMM (single fp16):
//   C[M,Ntot] = act( A[M,K] @ B^T + bias ),  A fp16 [M,K], B fp16 [Ntot,K].
// CTA tile 128x128, K-tile 64, 8 warps in 4(m) x 2(n); warp tile 32 x 64.
// 2-stage cp.async double buffer, XOR-8 swizzled 128B smem rows.
// ---------------------------------------------------------------------------
#define KT 64
#define A_BYTES  16384                 // 128 rows x 128 B
#define STAGE_BYTES (2 * A_BYTES)      // A + B = 32768
#define HMMA_SMEM (2 * STAGE_BYTES)    // 65536

template <int OUT>
__global__ __launch_bounds__(256, 2)
void hmma_gemm(const __half* __restrict__ A, const __half* __restrict__ B,
               const float* __restrict__ bias,
               float* __restrict__ Cf, __half* __restrict__ Ch,
               int K, int Ntot)
{
    extern __shared__ char smem_raw[];
    const uint32_t sbase = smem_u32(smem_raw);

    const int tid  = threadIdx.x;
    const int lane = tid & 31;
    const int wid  = tid >> 5;
    const int wm   = wid & 3;          // 4 warps along M (32 rows each)
    const int wn   = wid >> 2;         // 2 warps along N (64 cols each)
    const int bm   = blockIdx.y * 128;
    const int bn   = blockIdx.x * 128;
    const int nst  = K / KT;

    float acc[2][8][4];
#pragma unroll
    for (int i = 0; i < 2; i++)
#pragma unroll
        for (int j = 0; j < 8; j++)
#pragma unroll
            for (int q = 0; q < 4; q++) acc[i][j][q] = 0.0f;

    // ---- stage loader: 2 x 1024 16B chunks (A, B), 8 per thread -------------
    auto load_stage = [&](int i, int s) {
        const int kl = i * KT;
        const uint32_t sA = sbase + s * STAGE_BYTES;
        const uint32_t sB = sA + A_BYTES;
#pragma unroll
        for (int p = 0; p < 4; p++) {
            const int idx = p * 256 + tid;
            const int r = idx >> 3, c = idx & 7;
            const uint32_t so = r * 128 + ((c ^ (r & 7)) << 4);
            cp_async16(sA + so, A + (size_t)(bm + r) * K + kl + c * 8);
            cp_async16(sB + so, B + (size_t)(bn + r) * K + kl + c * 8);
        }
        CP_COMMIT();
    };

    load_stage(0, 0);
    if (nst > 1) load_stage(1, 1);

    for (int i = 0; i < nst; i++) {
        const int s = i & 1;
        if (i + 1 < nst) { CP_WAIT(1); } else { CP_WAIT(0); }
        __syncthreads();

        const uint32_t sA = sbase + s * STAGE_BYTES;
        const uint32_t sB = sA + A_BYTES;

#pragma unroll
        for (int ks = 0; ks < KT / 16; ks++) {
            // A fragments: 2 m16 tiles
            uint32_t a[2][4];
#pragma unroll
            for (int mt = 0; mt < 2; mt++) {
                const int row = wm * 32 + mt * 16 + (lane & 15);
                const int ch  = ks * 2 + (lane >> 4);
                ldsm_x4(a[mt], sA + row * 128 + ((ch ^ (row & 7)) << 4));
            }
            // B fragments: 4 x ldmatrix.x4
            uint32_t b[4][4];
#pragma unroll
            for (int np = 0; np < 4; np++) {
                const int nrow = wn * 64 + np * 16 + ((lane >> 4) << 3) + (lane & 7);
                const int ch   = ks * 2 + ((lane >> 3) & 1);
                ldsm_x4(b[np], sB + nrow * 128 + ((ch ^ (nrow & 7)) << 4));
            }
#pragma unroll
            for (int mt = 0; mt < 2; mt++)
#pragma unroll
                for (int np = 0; np < 4; np++) {
                    mma16816(acc[mt][np * 2 + 0], a[mt], &b[np][0]);
                    mma16816(acc[mt][np * 2 + 1], a[mt], &b[np][2]);
                }
        }
        __syncthreads();
        if (i + 2 < nst) load_stage(i + 2, s);
    }

    // ---- epilogue ----
    const int q  = lane & 3;
    const int r4 = lane >> 2;
#pragma unroll
    for (int mt = 0; mt < 2; mt++) {
#pragma unroll
        for (int nt = 0; nt < 8; nt++) {
            const int row0 = bm + wm * 32 + mt * 16 + r4;
            const int col  = bn + wn * 64 + nt * 8 + q * 2;
            const float b0 = bias[col], b1 = bias[col + 1];
            float d0 = acc[mt][nt][0] + b0;
            float d1 = acc[mt][nt][1] + b1;
            float d2 = acc[mt][nt][2] + b0;
            float d3 = acc[mt][nt][3] + b1;
            if (OUT == 0) {
                *reinterpret_cast<float2*>(Cf + (size_t)row0 * Ntot + col) =
                    make_float2(d0, d1);
                *reinterpret_cast<float2*>(Cf + (size_t)(row0 + 8) * Ntot + col) =
                    make_float2(d2, d3);
            } else {
                *reinterpret_cast<__half2*>(Ch + (size_t)row0 * Ntot + col) =
                    __halves2half2(__float2half_rn(tanhf(d0)), __float2half_rn(tanhf(d1)));
                *reinterpret_cast<__half2*>(Ch + (size_t)(row0 + 8) * Ntot + col) =
                    __halves2half2(__float2half_rn(tanhf(d2)), __float2half_rn(tanhf(d3)));
            }
        }
    }
}

// ---------------------------------------------------------------------------
// Prep kernels
// ---------------------------------------------------------------------------
// states fp32 [BATCH, SDIM] -> fp16 [BATCH, K1PAD] zero-padded
__global__ __launch_bounds__(256)
void pad_states(const float* __restrict__ S, __half* __restrict__ P)
{
    const int idx = blockIdx.x * 256 + threadIdx.x;   // one per output element
    const int m = idx >> 7, k = idx & 127;
    if (m < BATCH)
        P[idx] = (k < SDIM) ? __float2half_rn(S[(size_t)m * SDIM + k]) : __half(0.0f);
}

// W1 fp32 [SDIM, HID] -> W1T fp16 [HID, K1PAD] zero-padded
__global__ __launch_bounds__(256)
void pad_w1t(const float* __restrict__ W, __half* __restrict__ T)
{
    const int idx = blockIdx.x * 256 + threadIdx.x;
    const int n = idx >> 7, k = idx & 127;
    if (n < HID)
        T[idx] = (k < SDIM) ? __float2half_rn(W[(size_t)k * HID + n]) : __half(0.0f);
}

// W[K,N] fp32 -> Wt [N,K] fp16 (transpose + round)
__global__ void transpose_half(const float* __restrict__ W,
                               __half* __restrict__ T, int K, int N)
{
    __shared__ float t[32][33];
    const int k0 = blockIdx.x * 32, n0 = blockIdx.y * 32;
    const int tx = threadIdx.x, ty = threadIdx.y;
    for (int j = ty; j < 32; j += 8)
        t[j][tx] = W[(size_t)(k0 + j) * N + n0 + tx];
    __syncthreads();
    for (int j = ty; j < 32; j += 8)
        T[(size_t)(n0 + j) * K + k0 + tx] = __float2half_rn(t[tx][j]);
}

// ---------------------------------------------------------------------------
// In-place masked softmax — float4 vectorized (16 consecutive actions/thread)
// ---------------------------------------------------------------------------
__global__ __launch_bounds__(256)
void masked_softmax(float* __restrict__ out, const float* __restrict__ states)
{
    const int row = blockIdx.x;
    const int tid = threadIdx.x;

    __shared__ float sred[32];
    __shared__ int scap[6];

    if (tid < 6) scap[tid] = (int)floorf(states[(size_t)row * SDIM + NS + tid]);
    __syncthreads();

    const int c0 = scap[0], c1 = scap[1], c2 = scap[2];
    const int c3 = scap[3], c4 = scap[4], c5 = scap[5];

    float* rowp = out + (size_t)row * NACT;
    const int base = tid * 16;

    float vals[16];
    float mx = -INFINITY;

#pragma unroll
    for (int v4i = 0; v4i < 4; v4i++) {
        float4 v = *reinterpret_cast<const float4*>(rowp + base + v4i * 4);
        float* vp = reinterpret_cast<float*>(&v);
#pragma unroll
        for (int c = 0; c < 4; c++) {
            const int a = base + v4i * 4 + c;
            bool feas = (((a >> 10) & 3) <= c0) && (((a >> 8) & 3) <= c1) &&
                        (((a >> 6) & 3) <= c2) && (((a >> 4) & 3) <= c3) &&
                        (((a >> 2) & 3) <= c4) && (((a) & 3) <= c5);
            float x = vp[c];
            if (!feas) x += LOG_EPS;
            vals[v4i * 4 + c] = x;
            mx = fmaxf(mx, x);
        }
    }

#pragma unroll
    for (int o = 16; o > 0; o >>= 1) mx = fmaxf(mx, __shfl_xor_sync(0xffffffffu, mx, o));
    if ((tid & 31) == 0) sred[tid >> 5] = mx;
    __syncthreads();
    if (tid < 32) {
        float m = (tid < 8) ? sred[tid] : -INFINITY;
#pragma unroll
        for (int o = 4; o > 0; o >>= 1) m = fmaxf(m, __shfl_xor_sync(0xffffffffu, m, o));
        if (tid == 0) sred[0] = m;
    }
    __syncthreads();
    mx = sred[0];
    __syncthreads();

    float sum = 0.0f;
#pragma unroll
    for (int i = 0; i < 16; i++) { vals[i] = expf(vals[i] - mx); sum += vals[i]; }

#pragma unroll
    for (int o = 16; o > 0; o >>= 1) sum += __shfl_xor_sync(0xffffffffu, sum, o);
    if ((tid & 31) == 0) sred[tid >> 5] = sum;
    __syncthreads();
    if (tid < 32) {
        float s = (tid < 8) ? sred[tid] : 0.0f;
#pragma unroll
        for (int o = 4; o > 0; o >>= 1) s += __shfl_xor_sync(0xffffffffu, s, o);
        if (tid == 0) sred[0] = s;
    }
    __syncthreads();
    const float inv = 1.0f / sred[0];

#pragma unroll
    for (int v4i = 0; v4i < 4; v4i++) {
        float4 o4;
        o4.x = vals[v4i * 4 + 0] * inv;
        o4.y = vals[v4i * 4 + 1] * inv;
        o4.z = vals[v4i * 4 + 2] * inv;
        o4.w = vals[v4i * 4 + 3] * inv;
        *reinterpret_cast<float4*>(rowp + base + v4i * 4) = o4;
    }
}

// ---------------------------------------------------------------------------
extern "C" void kernel_launch(void* const* d_in, const int* in_sizes, int n_in,
                              void* d_out, int out_size)
{
    const float* states = (const float*)d_in[0];
    const float* W1     = (const float*)d_in[1];
    const float* b1     = (const float*)d_in[2];
    const float* W2     = (const float*)d_in[3];
    const float* b2     = (const float*)d_in[4];
    const float* Wh     = (const float*)d_in[5];
    const float* bh     = (const float*)d_in[6];
    float* out = (float*)d_out;

    __half *sp, *W1T, *h1, *h2, *W2T, *WhT;
    cudaGetSymbolAddress((void**)&sp,  g_sp);
    cudaGetSymbolAddress((void**)&W1T, g_W1T);
    cudaGetSymbolAddress((void**)&h1,  g_h1);
    cudaGetSymbolAddress((void**)&h2,  g_h2);
    cudaGetSymbolAddress((void**)&W2T, g_W2T);
    cudaGetSymbolAddress((void**)&WhT, g_WhT);

    cudaFuncSetAttribute(hmma_gemm<0>, cudaFuncAttributeMaxDynamicSharedMemorySize, HMMA_SMEM);
    cudaFuncSetAttribute(hmma_gemm<1>, cudaFuncAttributeMaxDynamicSharedMemorySize, HMMA_SMEM);

    // prep: pad states + W1^T, transpose W2/Wh to fp16 K-major
    pad_states<<<(BATCH * K1PAD) / 256, 256>>>(states, sp);
    pad_w1t<<<(HID * K1PAD) / 256, 256>>>(W1, W1T);
    transpose_half<<<dim3(HID / 32, HID / 32), dim3(32, 8)>>>(W2, W2T, HID, HID);
    transpose_half<<<dim3(HID / 32, NACT / 32), dim3(32, 8)>>>(Wh, WhT, HID, NACT);

    // layer 1 (HMMA, K=128 padded) -> h1 fp16
    hmma_gemm<1><<<dim3(HID / 128, BATCH / 128), 256, HMMA_SMEM>>>(
        sp, W1T, b1, nullptr, h1, K1PAD, HID);
    // layer 2 (HMMA) -> h2 fp16
    hmma_gemm<1><<<dim3(HID / 128, BATCH / 128), 256, HMMA_SMEM>>>(
        h1, W2T, b2, nullptr, h2, HID, HID);
    // head (HMMA) -> logits fp32 straight into d_out
    hmma_gemm<0><<<dim3(NACT / 128, BATCH / 128), 256, HMMA_SMEM>>>(
        h2, WhT, bh, out, nullptr, HID, NACT);
    // masked softmax in place
    masked_softmax<<<BATCH, 256>>>(out, states);
}

// round 9
// speedup vs baseline: 2.8863x; 1.1461x over previous
#include <cuda_runtime.h>
#include <cuda_fp16.h>
#include <math.h>
#include <stdint.h>

// Problem constants
#define BATCH 8192
#define SDIM  70
#define NS    64
#define HID   1024
#define NACT  4096
#define K1PAD 128                        // K=70 zero-padded for HMMA layer 1
#define LOG_EPS (-20.723265836946407f)   // logf(1e-9f)

// ---------------------------------------------------------------------------
// Scratch (allocation-free __device__ globals)
// ---------------------------------------------------------------------------
__device__ __align__(16) __half g_sp[BATCH * K1PAD];    // states fp16, K-padded
__device__ __align__(16) __half g_W1T[HID * K1PAD];     // W1^T fp16, K-padded
__device__ __align__(16) __half g_h1[BATCH * HID];
__device__ __align__(16) __half g_h2[BATCH * HID];
__device__ __align__(16) __half g_W2T[HID * HID];
__device__ __align__(16) __half g_WhT[NACT * HID];

// ---------------------------------------------------------------------------
// Helpers (plain sm_80+ PTX only — nothing sm_103a-conditional)
// ---------------------------------------------------------------------------
__device__ __forceinline__ uint32_t smem_u32(const void* p) {
    uint32_t a;
    asm("{ .reg .u64 t; cvta.to.shared.u64 t, %1; cvt.u32.u64 %0, t; }" : "=r"(a) : "l"(p));
    return a;
}

__device__ __forceinline__ void cp_async16(uint32_t saddr, const void* gaddr) {
    asm volatile("cp.async.cg.shared.global [%0], [%1], 16;" :: "r"(saddr), "l"(gaddr));
}
#define CP_COMMIT()  asm volatile("cp.async.commit_group;" ::: "memory")
#define CP_WAIT(n)   asm volatile("cp.async.wait_group %0;" :: "n"(n) : "memory")

__device__ __forceinline__ void ldsm_x4(uint32_t* r, uint32_t addr) {
    asm volatile("ldmatrix.sync.aligned.m8n8.x4.shared.b16 {%0,%1,%2,%3}, [%4];"
        : "=r"(r[0]), "=r"(r[1]), "=r"(r[2]), "=r"(r[3]) : "r"(addr));
}

__device__ __forceinline__ void mma16816(float* d, const uint32_t* a, const uint32_t* b) {
    asm volatile("mma.sync.aligned.m16n8k16.row.col.f32.f16.f16.f32 "
        "{%0,%1,%2,%3}, {%4,%5,%6,%7}, {%8,%9}, {%0,%1,%2,%3};"
        : "+f"(d[0]), "+f"(d[1]), "+f"(d[2]), "+f"(d[3])
        : "r"(a[0]), "r"(a[1]), "r"(a[2]), "r"(a[3]), "r"(b[0]), "r"(b[1]));
}

// ---------------------------------------------------------------------------
// HMMA GEMM (single fp16), NST = K/64 as a template parameter:
//   C[M,Ntot] = act( A[M,K] @ B^T + bias ),  A fp16 [M,K], B fp16 [Ntot,K].
// CTA tile 128x128, K-tile 64, 8 warps in 4(m) x 2(n); warp tile 32 x 64.
// 3-stage cp.async ring, ONE __syncthreads per K-tile (refill slot (i+2)%3
// holds stage i-1, drained by the pre-compute barrier). Fully unrolled outer
// loop -> all stage offsets compile-time. XOR-8 swizzled 128B smem rows.
// ---------------------------------------------------------------------------
#define KT 64
#define A_BYTES  16384                 // 128 rows x 128 B
#define STAGE_BYTES (2 * A_BYTES)      // A + B = 32768
#define NSTAGE 3
#define HMMA_SMEM (NSTAGE * STAGE_BYTES)   // 98304

template <int OUT, int NST>
__global__ __launch_bounds__(256, 2)
void hmma_gemm(const __half* __restrict__ A, const __half* __restrict__ B,
               const float* __restrict__ bias,
               float* __restrict__ Cf, __half* __restrict__ Ch,
               int Ntot)
{
    constexpr int K = NST * KT;
    extern __shared__ char smem_raw[];
    const uint32_t sbase = smem_u32(smem_raw);

    const int tid  = threadIdx.x;
    const int lane = tid & 31;
    const int wid  = tid >> 5;
    const int wm   = wid & 3;          // 4 warps along M (32 rows each)
    const int wn   = wid >> 2;         // 2 warps along N (64 cols each)
    const int bm   = blockIdx.y * 128;
    const int bn   = blockIdx.x * 128;

    float acc[2][8][4];
#pragma unroll
    for (int i = 0; i < 2; i++)
#pragma unroll
        for (int j = 0; j < 8; j++)
#pragma unroll
            for (int q = 0; q < 4; q++) acc[i][j][q] = 0.0f;

    // ---- stage loader: 2 x 1024 16B chunks (A, B), 8 per thread -------------
    auto load_stage = [&](int i, int s) {
        const int kl = i * KT;
        const uint32_t sA = sbase + s * STAGE_BYTES;
        const uint32_t sB = sA + A_BYTES;
#pragma unroll
        for (int p = 0; p < 4; p++) {
            const int idx = p * 256 + tid;
            const int r = idx >> 3, c = idx & 7;
            const uint32_t so = r * 128 + ((c ^ (r & 7)) << 4);
            cp_async16(sA + so, A + (size_t)(bm + r) * K + kl + c * 8);
            cp_async16(sB + so, B + (size_t)(bn + r) * K + kl + c * 8);
        }
        CP_COMMIT();
    };

    load_stage(0, 0);
    if (NST > 1) load_stage(1, 1);

#pragma unroll
    for (int i = 0; i < NST; i++) {
        const int s = i % NSTAGE;
        if (i + 1 < NST) { CP_WAIT(1); } else { CP_WAIT(0); }
        __syncthreads();

        // refill the slot drained at iter i-1 (stage i+2 -> slot (i+2)%3)
        if (i + 2 < NST) load_stage(i + 2, (i + 2) % NSTAGE);

        const uint32_t sA = sbase + s * STAGE_BYTES;
        const uint32_t sB = sA + A_BYTES;

#pragma unroll
        for (int ks = 0; ks < KT / 16; ks++) {
            // A fragments: 2 m16 tiles
            uint32_t a[2][4];
#pragma unroll
            for (int mt = 0; mt < 2; mt++) {
                const int row = wm * 32 + mt * 16 + (lane & 15);
                const int ch  = ks * 2 + (lane >> 4);
                ldsm_x4(a[mt], sA + row * 128 + ((ch ^ (row & 7)) << 4));
            }
            // B fragments: 4 x ldmatrix.x4
            uint32_t b[4][4];
#pragma unroll
            for (int np = 0; np < 4; np++) {
                const int nrow = wn * 64 + np * 16 + ((lane >> 4) << 3) + (lane & 7);
                const int ch   = ks * 2 + ((lane >> 3) & 1);
                ldsm_x4(b[np], sB + nrow * 128 + ((ch ^ (nrow & 7)) << 4));
            }
#pragma unroll
            for (int mt = 0; mt < 2; mt++)
#pragma unroll
                for (int np = 0; np < 4; np++) {
                    mma16816(acc[mt][np * 2 + 0], a[mt], &b[np][0]);
                    mma16816(acc[mt][np * 2 + 1], a[mt], &b[np][2]);
                }
        }
    }

    // ---- epilogue ----
    const int q  = lane & 3;
    const int r4 = lane >> 2;
#pragma unroll
    for (int mt = 0; mt < 2; mt++) {
#pragma unroll
        for (int nt = 0; nt < 8; nt++) {
            const int row0 = bm + wm * 32 + mt * 16 + r4;
            const int col  = bn + wn * 64 + nt * 8 + q * 2;
            const float b0 = bias[col], b1 = bias[col + 1];
            float d0 = acc[mt][nt][0] + b0;
            float d1 = acc[mt][nt][1] + b1;
            float d2 = acc[mt][nt][2] + b0;
            float d3 = acc[mt][nt][3] + b1;
            if (OUT == 0) {
                *reinterpret_cast<float2*>(Cf + (size_t)row0 * Ntot + col) =
                    make_float2(d0, d1);
                *reinterpret_cast<float2*>(Cf + (size_t)(row0 + 8) * Ntot + col) =
                    make_float2(d2, d3);
            } else {
                *reinterpret_cast<__half2*>(Ch + (size_t)row0 * Ntot + col) =
                    __halves2half2(__float2half_rn(tanhf(d0)), __float2half_rn(tanhf(d1)));
                *reinterpret_cast<__half2*>(Ch + (size_t)(row0 + 8) * Ntot + col) =
                    __halves2half2(__float2half_rn(tanhf(d2)), __float2half_rn(tanhf(d3)));
            }
        }
    }
}

// ---------------------------------------------------------------------------
// Prep kernels
// ---------------------------------------------------------------------------
// states fp32 [BATCH, SDIM] -> fp16 [BATCH, K1PAD] zero-padded
__global__ __launch_bounds__(256)
void pad_states(const float* __restrict__ S, __half* __restrict__ P)
{
    const int idx = blockIdx.x * 256 + threadIdx.x;
    const int m = idx >> 7, k = idx & 127;
    if (m < BATCH)
        P[idx] = (k < SDIM) ? __float2half_rn(S[(size_t)m * SDIM + k]) : __half(0.0f);
}

// W1 fp32 [SDIM, HID] -> W1T fp16 [HID, K1PAD] zero-padded
__global__ __launch_bounds__(256)
void pad_w1t(const float* __restrict__ W, __half* __restrict__ T)
{
    const int idx = blockIdx.x * 256 + threadIdx.x;
    const int n = idx >> 7, k = idx & 127;
    if (n < HID)
        T[idx] = (k < SDIM) ? __float2half_rn(W[(size_t)k * HID + n]) : __half(0.0f);
}

// W[K,N] fp32 -> Wt [N,K] fp16; 64(k) x 32(n) tiles, half2 stores.
__global__ __launch_bounds__(256)
void transpose_half(const float* __restrict__ W,
                    __half* __restrict__ T, int K, int N)
{
    __shared__ float t[64][33];
    const int k0 = blockIdx.x * 64, n0 = blockIdx.y * 32;
    const int tx = threadIdx.x, ty = threadIdx.y;   // 32 x 8
#pragma unroll
    for (int j = 0; j < 8; j++)                      // 64 k-rows
        t[ty * 8 + j][tx] = W[(size_t)(k0 + ty * 8 + j) * N + n0 + tx];
    __syncthreads();
#pragma unroll
    for (int j = 0; j < 4; j++) {                    // 32 n-rows
        const int n = ty + j * 8;
        __half2 v = __halves2half2(__float2half_rn(t[tx * 2][n]),
                                   __float2half_rn(t[tx * 2 + 1][n]));
        *reinterpret_cast<__half2*>(&T[(size_t)(n0 + n) * K + k0 + tx * 2]) = v;
    }
}

// ---------------------------------------------------------------------------
// In-place masked softmax — float4 vectorized (16 consecutive actions/thread)
// ---------------------------------------------------------------------------
__global__ __launch_bounds__(256)
void masked_softmax(float* __restrict__ out, const float* __restrict__ states)
{
    const int row = blockIdx.x;
    const int tid = threadIdx.x;

    __shared__ float sred[32];
    __shared__ int scap[6];

    if (tid < 6) scap[tid] = (int)floorf(states[(size_t)row * SDIM + NS + tid]);
    __syncthreads();

    const int c0 = scap[0], c1 = scap[1], c2 = scap[2];
    const int c3 = scap[3], c4 = scap[4], c5 = scap[5];

    float* rowp = out + (size_t)row * NACT;
    const int base = tid * 16;

    float vals[16];
    float mx = -INFINITY;

#pragma unroll
    for (int v4i = 0; v4i < 4; v4i++) {
        float4 v = *reinterpret_cast<const float4*>(rowp + base + v4i * 4);
        float* vp = reinterpret_cast<float*>(&v);
#pragma unroll
        for (int c = 0; c < 4; c++) {
            const int a = base + v4i * 4 + c;
            bool feas = (((a >> 10) & 3) <= c0) && (((a >> 8) & 3) <= c1) &&
                        (((a >> 6) & 3) <= c2) && (((a >> 4) & 3) <= c3) &&
                        (((a >> 2) & 3) <= c4) && (((a) & 3) <= c5);
            float x = vp[c];
            if (!feas) x += LOG_EPS;
            vals[v4i * 4 + c] = x;
            mx = fmaxf(mx, x);
        }
    }

#pragma unroll
    for (int o = 16; o > 0; o >>= 1) mx = fmaxf(mx, __shfl_xor_sync(0xffffffffu, mx, o));
    if ((tid & 31) == 0) sred[tid >> 5] = mx;
    __syncthreads();
    if (tid < 32) {
        float m = (tid < 8) ? sred[tid] : -INFINITY;
#pragma unroll
        for (int o = 4; o > 0; o >>= 1) m = fmaxf(m, __shfl_xor_sync(0xffffffffu, m, o));
        if (tid == 0) sred[0] = m;
    }
    __syncthreads();
    mx = sred[0];
    __syncthreads();

    float sum = 0.0f;
#pragma unroll
    for (int i = 0; i < 16; i++) { vals[i] = expf(vals[i] - mx); sum += vals[i]; }

#pragma unroll
    for (int o = 16; o > 0; o >>= 1) sum += __shfl_xor_sync(0xffffffffu, sum, o);
    if ((tid & 31) == 0) sred[tid >> 5] = sum;
    __syncthreads();
    if (tid < 32) {
        float s = (tid < 8) ? sred[tid] : 0.0f;
#pragma unroll
        for (int o = 4; o > 0; o >>= 1) s += __shfl_xor_sync(0xffffffffu, s, o);
        if (tid == 0) sred[0] = s;
    }
    __syncthreads();
    const float inv = 1.0f / sred[0];

#pragma unroll
    for (int v4i = 0; v4i < 4; v4i++) {
        float4 o4;
        o4.x = vals[v4i * 4 + 0] * inv;
        o4.y = vals[v4i * 4 + 1] * inv;
        o4.z = vals[v4i * 4 + 2] * inv;
        o4.w = vals[v4i * 4 + 3] * inv;
        *reinterpret_cast<float4*>(rowp + base + v4i * 4) = o4;
    }
}

// ---------------------------------------------------------------------------
extern "C" void kernel_launch(void* const* d_in, const int* in_sizes, int n_in,
                              void* d_out, int out_size)
{
    const float* states = (const float*)d_in[0];
    const float* W1     = (const float*)d_in[1];
    const float* b1     = (const float*)d_in[2];
    const float* W2     = (const float*)d_in[3];
    const float* b2     = (const float*)d_in[4];
    const float* Wh     = (const float*)d_in[5];
    const float* bh     = (const float*)d_in[6];
    float* out = (float*)d_out;

    __half *sp, *W1T, *h1, *h2, *W2T, *WhT;
    cudaGetSymbolAddress((void**)&sp,  g_sp);
    cudaGetSymbolAddress((void**)&W1T, g_W1T);
    cudaGetSymbolAddress((void**)&h1,  g_h1);
    cudaGetSymbolAddress((void**)&h2,  g_h2);
    cudaGetSymbolAddress((void**)&W2T, g_W2T);
    cudaGetSymbolAddress((void**)&WhT, g_WhT);

    cudaFuncSetAttribute((const void*)hmma_gemm<1, 2>,
                         cudaFuncAttributeMaxDynamicSharedMemorySize, HMMA_SMEM);
    cudaFuncSetAttribute((const void*)hmma_gemm<1, 16>,
                         cudaFuncAttributeMaxDynamicSharedMemorySize, HMMA_SMEM);
    cudaFuncSetAttribute((const void*)hmma_gemm<0, 16>,
                         cudaFuncAttributeMaxDynamicSharedMemorySize, HMMA_SMEM);

    // prep: pad states + W1^T, transpose W2/Wh to fp16 K-major
    pad_states<<<(BATCH * K1PAD) / 256, 256>>>(states, sp);
    pad_w1t<<<(HID * K1PAD) / 256, 256>>>(W1, W1T);
    transpose_half<<<dim3(HID / 64, HID / 32), dim3(32, 8)>>>(W2, W2T, HID, HID);
    transpose_half<<<dim3(HID / 64, NACT / 32), dim3(32, 8)>>>(Wh, WhT, HID, NACT);

    // layer 1 (HMMA, K=128 padded) -> h1 fp16
    hmma_gemm<1, 2><<<dim3(HID / 128, BATCH / 128), 256, HMMA_SMEM>>>(
        sp, W1T, b1, nullptr, h1, HID);
    // layer 2 (HMMA) -> h2 fp16
    hmma_gemm<1, 16><<<dim3(HID / 128, BATCH / 128), 256, HMMA_SMEM>>>(
        h1, W2T, b2, nullptr, h2, HID);
    // head (HMMA) -> logits fp32 straight into d_out
    hmma_gemm<0, 16><<<dim3(NACT / 128, BATCH / 128), 256, HMMA_SMEM>>>(
        h2, WhT, bh, out, nullptr, NACT);
    // masked softmax in place
    masked_softmax<<<BATCH, 256>>>(out, states);
}